// round 1
// baseline (speedup 1.0000x reference)
#include <cuda_runtime.h>
#include <math.h>

#define NI   128
#define ND   32
#define NH   4
#define NNEI 120
#define MAXLOC 2048
#define HC   (NH * NI)   // 512

// ---------------- scratch (device globals: no allocation allowed) ----------------
__device__ float d_Mq[NI * HC];       // 128 x 512 : combined q/k projection (incl 1/sqrt(ND))
__device__ float d_W2[HC * NI];       // 512 x 128 : combined v-projection @ Wh
__device__ float d_QW[MAXLOC * HC];   // 2048 x 512
__device__ float d_Aat[MAXLOC * HC];  // 2048 x 512

// ---------------- K0: precompute Mq and W2 ----------------
// Mq[e, h*128+c] = (1/sqrt(32)) * sum_d Wq[e, d*4+h] * Wkv[c, d*4+h]
// W2[h*128+c, i] = sum_ip Wkv[c, (32+ip)*4+h] * Wh[h*128+ip, i]
__global__ void precompute_kernel(const float* __restrict__ Wq,
                                  const float* __restrict__ Wkv,
                                  const float* __restrict__ Wh)
{
    int gid = blockIdx.x * blockDim.x + threadIdx.x;
    if (gid < NI * HC) {
        int e = gid >> 9;
        int hc = gid & 511;
        int h = hc >> 7;
        int c = hc & 127;
        float s = 0.f;
#pragma unroll
        for (int d = 0; d < ND; d++)
            s += Wq[e * 128 + d * 4 + h] * Wkv[c * 640 + d * 4 + h];
        d_Mq[gid] = s * 0.17677669529663687f;   // 1/sqrt(32)
    } else {
        int g = gid - NI * HC;
        int r = g >> 7;          // h*128 + c
        int i = g & 127;
        int h = r >> 7;
        int c = r & 127;
        float s = 0.f;
#pragma unroll 8
        for (int ip = 0; ip < 128; ip++)
            s += Wkv[c * 640 + (32 + ip) * 4 + h] * Wh[(h * 128 + ip) * 128 + i];
        d_W2[g] = s;
    }
}

// ---------------- generic 64x64 tiled SGEMM (M,N %64==0, K %16==0) ----------------
__global__ __launch_bounds__(256) void sgemm64(const float* __restrict__ A,
                                               const float* __restrict__ B,
                                               float* __restrict__ C,
                                               int M, int N, int K,
                                               const float* __restrict__ bias)
{
    __shared__ float As[16][64];   // As[k][m] (A tile transposed)
    __shared__ float Bs[16][64];   // Bs[k][n]
    int t = threadIdx.x;
    int tx = t & 15, ty = t >> 4;
    int rowBase = blockIdx.y * 64, colBase = blockIdx.x * 64;
    int arow = t >> 2, ak = (t & 3) << 2;
    int bk = t >> 4, bn = (t & 15) << 2;

    float acc00=0,acc01=0,acc02=0,acc03=0;
    float acc10=0,acc11=0,acc12=0,acc13=0;
    float acc20=0,acc21=0,acc22=0,acc23=0;
    float acc30=0,acc31=0,acc32=0,acc33=0;

    for (int kk = 0; kk < K; kk += 16) {
        float4 av = *(const float4*)&A[(size_t)(rowBase + arow) * K + kk + ak];
        As[ak + 0][arow] = av.x;
        As[ak + 1][arow] = av.y;
        As[ak + 2][arow] = av.z;
        As[ak + 3][arow] = av.w;
        *(float4*)&Bs[bk][bn] = *(const float4*)&B[(size_t)(kk + bk) * N + colBase + bn];
        __syncthreads();
#pragma unroll
        for (int k = 0; k < 16; k++) {
            float4 a = *(const float4*)&As[k][ty << 2];
            float4 b = *(const float4*)&Bs[k][tx << 2];
            acc00 += a.x * b.x; acc01 += a.x * b.y; acc02 += a.x * b.z; acc03 += a.x * b.w;
            acc10 += a.y * b.x; acc11 += a.y * b.y; acc12 += a.y * b.z; acc13 += a.y * b.w;
            acc20 += a.z * b.x; acc21 += a.z * b.y; acc22 += a.z * b.z; acc23 += a.z * b.w;
            acc30 += a.w * b.x; acc31 += a.w * b.y; acc32 += a.w * b.z; acc33 += a.w * b.w;
        }
        __syncthreads();
    }

    int col = colBase + (tx << 2);
    float bx = 0.f, by = 0.f, bz = 0.f, bw = 0.f;
    if (bias) { bx = bias[col]; by = bias[col + 1]; bz = bias[col + 2]; bw = bias[col + 3]; }
    int row = rowBase + (ty << 2);
    float4 o;
    o.x = acc00 + bx; o.y = acc01 + by; o.z = acc02 + bz; o.w = acc03 + bw;
    *(float4*)&C[(size_t)(row + 0) * N + col] = o;
    o.x = acc10 + bx; o.y = acc11 + by; o.z = acc12 + bz; o.w = acc13 + bw;
    *(float4*)&C[(size_t)(row + 1) * N + col] = o;
    o.x = acc20 + bx; o.y = acc21 + by; o.z = acc22 + bz; o.w = acc23 + bw;
    *(float4*)&C[(size_t)(row + 2) * N + col] = o;
    o.x = acc30 + bx; o.y = acc31 + by; o.z = acc32 + bz; o.w = acc33 + bw;
    *(float4*)&C[(size_t)(row + 3) * N + col] = o;
}

// ---------------- K2: fused per-location attention core ----------------
// smem layout (floats): ggs[120*132] | qws[512] | slog[512] | swt[512] | ssw[128] | smask[128 ints]
#define GG_STRIDE 132
#define SMEM_FLOATS (NNEI * GG_STRIDE + 512 + 512 + 512 + 128)
#define SMEM_BYTES  (SMEM_FLOATS * 4 + 128 * 4)

__global__ __launch_bounds__(512) void attn_kernel(const float* __restrict__ gg1,
                                                   const void* __restrict__ maskRaw,
                                                   const float* __restrict__ sw)
{
    extern __shared__ float sm[];
    float* ggs  = sm;                        // [120][132]
    float* qws  = ggs + NNEI * GG_STRIDE;    // [512]
    float* slog = qws + 512;                 // [4][128]
    float* swt  = slog + 512;                // [4][128]
    float* ssw  = swt + 512;                 // [128]
    int*  smask = (int*)(ssw + 128);         // [128]

    __shared__ int s_f12;   // nonzero bytes at offsets %4 in {1,2}  -> mask stored as 1-byte
    __shared__ int s_f3;    // nonzero bytes at offset %4 == 3       -> mask stored as float32

    int tid = threadIdx.x;
    int loc = blockIdx.x;

    if (tid == 0) { s_f12 = 0; s_f3 = 0; }
    __syncthreads();

    // --- mask dtype detection from first 1KB of the buffer (deterministic) ---
    if (tid < 64) {
        uint4 v = ((const uint4*)maskRaw)[tid];
        unsigned orw = v.x | v.y | v.z | v.w;
        if (orw & 0x00FFFF00u) atomicOr(&s_f12, 1);
        if (orw & 0xFF000000u) atomicOr(&s_f3, 1);
    }

    // --- load gg1 slab [120 x 128] into padded SMEM (coalesced float4) ---
    const float4* g4 = (const float4*)(gg1 + (size_t)loc * NNEI * NI);
    for (int idx = tid; idx < NNEI * 32; idx += 512) {
        int j = idx >> 5;
        int cq = idx & 31;
        *(float4*)&ggs[j * GG_STRIDE + cq * 4] = g4[idx];
    }
    // --- load qW row [512] ---
    if (tid < 128)
        *(float4*)&qws[tid * 4] = ((const float4*)(d_QW + (size_t)loc * HC))[tid];
    __syncthreads();

    int f12 = s_f12, f3 = s_f3;
    if (tid < NNEI) {
        size_t base = (size_t)loc * NNEI + tid;
        int m;
        if (f12)      m = ((const unsigned char*)maskRaw)[base] != 0;
        else if (f3)  m = ((const float*)maskRaw)[base] != 0.f;
        else          m = ((const int*)maskRaw)[base] != 0;
        smask[tid] = m;
        ssw[tid] = sw[base];
    }

    // --- logits[h][j] = qws[h,:] . ggs[j,:]  (480 length-128 dots) ---
    if (tid < NH * NNEI) {
        int h = tid / NNEI;
        int j = tid - h * NNEI;
        const float4* gr = (const float4*)&ggs[j * GG_STRIDE];
        const float4* qr = (const float4*)&qws[h * NI];
        float acc = 0.f;
#pragma unroll 8
        for (int k = 0; k < 32; k++) {
            float4 g = gr[k];
            float4 q = qr[k];
            acc += g.x * q.x + g.y * q.y + g.z * q.z + g.w * q.w;
        }
        slog[h * 128 + j] = acc;
    }
    __syncthreads();

    // --- masked softmax * sw, one warp per head ---
    if (tid < 128) {
        int h = tid >> 5;
        int lane = tid & 31;
        float lv[4];
        int mk[4];
        float mx = -INFINITY;
#pragma unroll
        for (int q = 0; q < 4; q++) {
            int j = lane + q * 32;
            int in = (j < NNEI) ? smask[j] : 0;
            float L = in ? slog[h * 128 + j] : -INFINITY;
            lv[q] = L;
            mk[q] = in;
            mx = fmaxf(mx, L);
        }
#pragma unroll
        for (int off = 16; off > 0; off >>= 1)
            mx = fmaxf(mx, __shfl_xor_sync(0xFFFFFFFFu, mx, off));
        float ev[4];
        float sum = 0.f;
#pragma unroll
        for (int q = 0; q < 4; q++) {
            ev[q] = mk[q] ? __expf(lv[q] - mx) : 0.f;
            sum += ev[q];
        }
#pragma unroll
        for (int off = 16; off > 0; off >>= 1)
            sum += __shfl_xor_sync(0xFFFFFFFFu, sum, off);
        float inv = (sum > 0.f) ? (1.f / sum) : 0.f;
#pragma unroll
        for (int q = 0; q < 4; q++) {
            int j = lane + q * 32;
            float w = (j < NNEI && mk[q]) ? ev[q] * inv * ssw[j] : 0.f;
            swt[h * 128 + j] = w;
        }
    }
    __syncthreads();

    // --- a[h][c] = sum_j w[h][j] * ggs[j][c]  (512 threads, one output each) ---
    {
        int h = tid >> 7;
        int c = tid & 127;
        const float* wrow = &swt[h * 128];
        float acc = 0.f;
#pragma unroll 4
        for (int j = 0; j < NNEI; j++)
            acc += wrow[j] * ggs[j * GG_STRIDE + c];
        d_Aat[(size_t)loc * HC + tid] = acc;
    }
}

// ---------------- launch ----------------
extern "C" void kernel_launch(void* const* d_in, const int* in_sizes, int n_in,
                              void* d_out, int out_size)
{
    const float* g1   = (const float*)d_in[0];
    const float* gg1  = (const float*)d_in[1];
    const void*  mask = d_in[2];
    const float* sw   = (const float*)d_in[3];
    const float* Wq   = (const float*)d_in[4];
    const float* Wkv  = (const float*)d_in[5];
    const float* Wh   = (const float*)d_in[6];
    const float* bh   = (const float*)d_in[7];
    float* out = (float*)d_out;

    int nloctot = in_sizes[0] / NI;   // 2048

    void *pMq, *pW2, *pQW, *pA;
    cudaGetSymbolAddress(&pMq, d_Mq);
    cudaGetSymbolAddress(&pW2, d_W2);
    cudaGetSymbolAddress(&pQW, d_QW);
    cudaGetSymbolAddress(&pA,  d_Aat);

    cudaFuncSetAttribute(attn_kernel, cudaFuncAttributeMaxDynamicSharedMemorySize, SMEM_BYTES);

    // K0: combined projection matrices (2*65536 outputs)
    precompute_kernel<<<512, 256>>>(Wq, Wkv, Wh);

    // K1: QW = g1 @ Mq   (nloctot x 512, K=128)
    sgemm64<<<dim3(HC / 64, nloctot / 64), 256>>>(g1, (const float*)pMq, (float*)pQW,
                                                  nloctot, HC, NI, nullptr);

    // K2: fused attention core -> d_Aat
    attn_kernel<<<nloctot, 512, SMEM_BYTES>>>(gg1, mask, sw);

    // K3: out = A @ W2 + bh   (nloctot x 128, K=512)
    sgemm64<<<dim3(NI / 64, nloctot / 64), 256>>>((const float*)pA, (const float*)pW2, out,
                                                  nloctot, NI, HC, bh);
}

// round 2
// speedup vs baseline: 1.2069x; 1.2069x over previous
#include <cuda_runtime.h>
#include <math.h>

#define NI   128
#define ND   32
#define NH   4
#define NNEI 120
#define HC   (NH * NI)   // 512
#define BLOC 8
#define NTHR 512
#define GG_STRIDE 132
#define SLAB (NNEI * GG_STRIDE)   // 15840 floats

// ---------------- scratch (device globals) ----------------
__device__ float d_Mq[NI * HC];       // 128 x 512 : combined q/k projection (incl 1/sqrt(32))
__device__ float d_W2[HC * NI];       // 512 x 128 : combined v-projection @ Wh

// ---------------- K0: precompute Mq and W2 ----------------
// Mq[e, h*128+c] = (1/sqrt(32)) * sum_d Wq[e, d*4+h] * Wkv[c, d*4+h]
// W2[h*128+c, i] = sum_ip Wkv[c, (32+ip)*4+h] * Wh[h*128+ip, i]
__global__ void precompute_kernel(const float* __restrict__ Wq,
                                  const float* __restrict__ Wkv,
                                  const float* __restrict__ Wh)
{
    int gid = blockIdx.x * blockDim.x + threadIdx.x;
    if (gid < NI * HC) {
        int e = gid >> 9;
        int hc = gid & 511;
        int h = hc >> 7;
        int c = hc & 127;
        float s = 0.f;
#pragma unroll
        for (int d = 0; d < ND; d++)
            s += Wq[e * 128 + d * 4 + h] * Wkv[c * 640 + d * 4 + h];
        d_Mq[gid] = s * 0.17677669529663687f;   // 1/sqrt(32)
    } else {
        int g = gid - NI * HC;
        int r = g >> 7;          // h*128 + c
        int i = g & 127;
        int h = r >> 7;
        int c = r & 127;
        float s = 0.f;
#pragma unroll 8
        for (int ip = 0; ip < 128; ip++)
            s += Wkv[c * 640 + (32 + ip) * 4 + h] * Wh[(h * 128 + ip) * 128 + i];
        d_W2[g] = s;
    }
}

// ---------------- fused kernel ----------------
// smem float offsets
#define OFF_GGS0  0
#define OFF_GGS1  SLAB
#define OFF_QW8   (2 * SLAB)            // 4096 floats (reused as epilogue partials)
#define OFF_A8T   (OFF_QW8 + 4096)      // 4096  a8t[k*8 + l]
#define OFF_G1S   (OFF_A8T + 4096)      // 1024
#define OFF_SPART (OFF_G1S + 1024)      // 2048
#define OFF_SWT4  (OFF_SPART + 2048)    // 512   swt4[j*4 + h]
#define OFF_SSW   (OFF_SWT4 + 512)      // 1024  ssw8[l*128 + j]
#define OFF_MASK  (OFF_SSW + 1024)      // 1024 ints
#define OFF_FLAG  (OFF_MASK + 1024)     // 2 ints
#define SMEM_FLOATS (OFF_FLAG + 8)
#define SMEM_BYTES  (SMEM_FLOATS * 4)   // ~182 KB

__device__ __forceinline__ void cp16(float* dst, const float* src)
{
    unsigned s = (unsigned)__cvta_generic_to_shared(dst);
    asm volatile("cp.async.cg.shared.global [%0], [%1], 16;\n" :: "r"(s), "l"(src));
}

__device__ __forceinline__ void issue_slab(float* dstb, const float* gb, int tid)
{
#pragma unroll
    for (int w = 0; w < 8; w++) {
        int idx = tid + w * NTHR;
        if (idx < NNEI * 32) {
            int j = idx >> 5, q = idx & 31;
            cp16(dstb + j * GG_STRIDE + q * 4, gb + idx * 4);
        }
    }
    asm volatile("cp.async.commit_group;\n" ::: "memory");
}

__global__ __launch_bounds__(NTHR, 1) void fused_attn(
    const float* __restrict__ g1,
    const float* __restrict__ gg1,
    const void*  __restrict__ maskRaw,
    const float* __restrict__ sw,
    const float* __restrict__ bh,
    float* __restrict__ out)
{
    extern __shared__ float sm[];
    float* qw8    = sm + OFF_QW8;
    float* a8t    = sm + OFF_A8T;
    float* g1s    = sm + OFF_G1S;
    float* spart  = sm + OFF_SPART;
    float* swt4   = sm + OFF_SWT4;
    float* ssw8   = sm + OFF_SSW;
    int*   smask8 = (int*)(sm + OFF_MASK);
    int*   sflag  = (int*)(sm + OFF_FLAG);

    const int tid = threadIdx.x;
    const int locbase = blockIdx.x * BLOC;

    if (tid == 0) { sflag[0] = 0; sflag[1] = 0; }

    // prefetch gg1 slabs for loc 0 and 1 into the two buffers
    issue_slab(sm + OFF_GGS0, gg1 + (size_t)(locbase + 0) * (NNEI * NI), tid);
    issue_slab(sm + OFF_GGS1, gg1 + (size_t)(locbase + 1) * (NNEI * NI), tid);
    __syncthreads();

    // --- mask dtype detection from first 1KB (deterministic) ---
    if (tid < 64) {
        uint4 v = ((const uint4*)maskRaw)[tid];
        unsigned orw = v.x | v.y | v.z | v.w;
        if (orw & 0x00FFFF00u) atomicOr(&sflag[0], 1);
        if (orw & 0xFF000000u) atomicOr(&sflag[1], 1);
    }
    // --- g1 rows for the 8 locs ---
    if (tid < 256) {
        int l = tid >> 5, e4 = tid & 31;
        *(float4*)&g1s[l * NI + e4 * 4] =
            *(const float4*)&g1[(size_t)(locbase + l) * NI + e4 * 4];
    }
    __syncthreads();

    // --- mask + sw for 8 locs ---
    {
        int f12 = sflag[0], f3 = sflag[1];
        for (int idx = tid; idx < BLOC * NNEI; idx += NTHR) {
            int l = idx / NNEI, j = idx - l * NNEI;
            size_t base = (size_t)(locbase + l) * NNEI + j;
            int m;
            if (f12)      m = ((const unsigned char*)maskRaw)[base] != 0;
            else if (f3)  m = ((const float*)maskRaw)[base] != 0.f;
            else          m = ((const int*)maskRaw)[base] != 0;
            smask8[l * NI + j] = m;
            ssw8[l * NI + j]   = sw[base];
        }
    }

    // --- qw8[l][n] = g1[l,:] . Mq[:,n]  (n = tid), overlaps slab prefetch ---
    {
        float acc[BLOC];
#pragma unroll
        for (int l = 0; l < BLOC; l++) acc[l] = 0.f;
        const float* mq = d_Mq + tid;
#pragma unroll 4
        for (int e = 0; e < NI; e++) {
            float m = mq[e * HC];
#pragma unroll
            for (int l = 0; l < BLOC; l++)
                acc[l] += g1s[l * NI + e] * m;
        }
#pragma unroll
        for (int l = 0; l < BLOC; l++) qw8[l * HC + tid] = acc[l];
    }
    __syncthreads();

    // ---------------- per-location loop ----------------
    for (int il = 0; il < BLOC; il++) {
        if (il < BLOC - 1) asm volatile("cp.async.wait_group 1;\n" ::: "memory");
        else               asm volatile("cp.async.wait_group 0;\n" ::: "memory");
        __syncthreads();
        float* ggb = sm + ((il & 1) ? OFF_GGS1 : OFF_GGS0);

        // --- logits partials: thread (kq, j) computes 4 head-partials over k-quarter ---
        if (tid < NH * NNEI) {
            int kq = tid / NNEI;
            int j  = tid - kq * NNEI;
            const float4* gr = (const float4*)(ggb + j * GG_STRIDE + kq * 32);
            const float4* q0 = (const float4*)(qw8 + il * HC + 0 * NI + kq * 32);
            const float4* q1 = (const float4*)(qw8 + il * HC + 1 * NI + kq * 32);
            const float4* q2 = (const float4*)(qw8 + il * HC + 2 * NI + kq * 32);
            const float4* q3 = (const float4*)(qw8 + il * HC + 3 * NI + kq * 32);
            float p0 = 0.f, p1 = 0.f, p2 = 0.f, p3 = 0.f;
#pragma unroll
            for (int i = 0; i < 8; i++) {
                float4 g = gr[i];
                float4 a = q0[i]; p0 += g.x*a.x + g.y*a.y + g.z*a.z + g.w*a.w;
                float4 b = q1[i]; p1 += g.x*b.x + g.y*b.y + g.z*b.z + g.w*b.w;
                float4 c = q2[i]; p2 += g.x*c.x + g.y*c.y + g.z*c.z + g.w*c.w;
                float4 d = q3[i]; p3 += g.x*d.x + g.y*d.y + g.z*d.z + g.w*d.w;
            }
            spart[kq * HC + 0 * NI + j] = p0;
            spart[kq * HC + 1 * NI + j] = p1;
            spart[kq * HC + 2 * NI + j] = p2;
            spart[kq * HC + 3 * NI + j] = p3;
        }
        __syncthreads();

        // --- masked softmax * sw (one warp per head), fusing the kq-reduce ---
        if (tid < 128) {
            int h = tid >> 5, lane = tid & 31;
            float lv[4]; int mk[4];
            float mx = -INFINITY;
#pragma unroll
            for (int q = 0; q < 4; q++) {
                int j = lane + q * 32;
                int in = (j < NNEI) ? smask8[il * NI + j] : 0;
                float L = -INFINITY;
                if (in) L = spart[h * NI + j] + spart[HC + h * NI + j]
                          + spart[2 * HC + h * NI + j] + spart[3 * HC + h * NI + j];
                lv[q] = L; mk[q] = in;
                mx = fmaxf(mx, L);
            }
#pragma unroll
            for (int off = 16; off > 0; off >>= 1)
                mx = fmaxf(mx, __shfl_xor_sync(0xFFFFFFFFu, mx, off));
            float ev[4];
            float sum = 0.f;
#pragma unroll
            for (int q = 0; q < 4; q++) {
                ev[q] = mk[q] ? __expf(lv[q] - mx) : 0.f;
                sum += ev[q];
            }
#pragma unroll
            for (int off = 16; off > 0; off >>= 1)
                sum += __shfl_xor_sync(0xFFFFFFFFu, sum, off);
            float inv = (sum > 0.f) ? (1.f / sum) : 0.f;
#pragma unroll
            for (int q = 0; q < 4; q++) {
                int j = lane + q * 32;
                if (j < NNEI) {
                    float w = mk[q] ? ev[q] * inv * ssw8[il * NI + j] : 0.f;
                    swt4[j * 4 + h] = w;
                }
            }
        }
        __syncthreads();

        // --- weighted sum: thread (jq, c) accumulates 4 heads over j-quarter ---
        {
            int c = tid & 127, jq = tid >> 7;
            const float* gcol = ggb + c;
            float s0 = 0.f, s1 = 0.f, s2 = 0.f, s3 = 0.f;
            int j0 = jq * 30;
#pragma unroll
            for (int j = 0; j < 30; j++) {
                float g = gcol[(j0 + j) * GG_STRIDE];
                float4 w = *(const float4*)&swt4[(j0 + j) * 4];
                s0 += w.x * g; s1 += w.y * g; s2 += w.z * g; s3 += w.w * g;
            }
            spart[jq * HC + 0 * NI + c] = s0;
            spart[jq * HC + 1 * NI + c] = s1;
            spart[jq * HC + 2 * NI + c] = s2;
            spart[jq * HC + 3 * NI + c] = s3;
        }
        __syncthreads();

        // --- reduce jq-partials into a8t[k][l], and prefetch slab il+2 ---
        a8t[tid * 8 + il] = spart[tid] + spart[HC + tid]
                          + spart[2 * HC + tid] + spart[3 * HC + tid];

        if (il + 2 < BLOC) {
            float* dstb = sm + ((il & 1) ? OFF_GGS1 : OFF_GGS0);
            issue_slab(dstb, gg1 + (size_t)(locbase + il + 2) * (NNEI * NI), tid);
        }
    }
    __syncthreads();

    // ---------------- fused output GEMM: out[8][128] = a[8][512] @ W2 + bh ----------------
    {
        int i = tid & 127, kq = tid >> 7;
        float acc[BLOC];
#pragma unroll
        for (int l = 0; l < BLOC; l++) acc[l] = 0.f;
        const float* w2p = d_W2 + (size_t)(kq * NI) * NI + i;
#pragma unroll 4
        for (int k = 0; k < 128; k++) {
            float w2 = w2p[k * NI];
            const float* ap = a8t + (kq * 128 + k) * 8;
            float4 lo = *(const float4*)ap;
            float4 hi = *(const float4*)(ap + 4);
            acc[0] += lo.x * w2; acc[1] += lo.y * w2;
            acc[2] += lo.z * w2; acc[3] += lo.w * w2;
            acc[4] += hi.x * w2; acc[5] += hi.y * w2;
            acc[6] += hi.z * w2; acc[7] += hi.w * w2;
        }
#pragma unroll
        for (int l = 0; l < BLOC; l++)
            qw8[kq * 1024 + l * NI + i] = acc[l];   // reuse qw8 as epilogue partials
    }
    __syncthreads();
    for (int o = tid; o < BLOC * NI; o += NTHR) {
        int l = o >> 7, ii = o & 127;
        float v = qw8[o] + qw8[1024 + o] + qw8[2048 + o] + qw8[3072 + o] + bh[ii];
        out[(size_t)(locbase + l) * NI + ii] = v;
    }
}

// ---------------- launch ----------------
extern "C" void kernel_launch(void* const* d_in, const int* in_sizes, int n_in,
                              void* d_out, int out_size)
{
    const float* g1   = (const float*)d_in[0];
    const float* gg1  = (const float*)d_in[1];
    const void*  mask = d_in[2];
    const float* sw   = (const float*)d_in[3];
    const float* Wq   = (const float*)d_in[4];
    const float* Wkv  = (const float*)d_in[5];
    const float* Wh   = (const float*)d_in[6];
    const float* bh   = (const float*)d_in[7];
    float* out = (float*)d_out;

    int nloctot = in_sizes[0] / NI;   // 2048

    static int smem_set = 0;
    if (!smem_set) {
        cudaFuncSetAttribute(fused_attn, cudaFuncAttributeMaxDynamicSharedMemorySize, SMEM_BYTES);
        smem_set = 1;
    }

    // K0: combined projection matrices
    precompute_kernel<<<512, 256>>>(Wq, Wkv, Wh);

    // fused: qw projection + attention + output GEMM
    fused_attn<<<nloctot / BLOC, NTHR, SMEM_BYTES>>>(g1, gg1, mask, sw, bh, out);
}

// round 3
// speedup vs baseline: 1.2542x; 1.0392x over previous
#include <cuda_runtime.h>
#include <math.h>

#define NI   128
#define ND   32
#define NH   4
#define NNEI 120
#define HC   (NH * NI)   // 512
#define BLOC 8
#define NTHR 512
#define GG_STRIDE 132
#define SLAB (NNEI * GG_STRIDE)       // 15840 floats
#define HROWS 60
#define HALF_F (HROWS * GG_STRIDE)    // half-slab floats

// ---------------- scratch (device globals) ----------------
__device__ float d_Mq[NI * HC];       // 128 x 512 : combined q/k projection (incl 1/sqrt(32))
__device__ float d_W2[HC * NI];       // 512 x 128 : combined v-projection @ Wh

// ---------------- K0: precompute Mq and W2 ----------------
__global__ void precompute_kernel(const float* __restrict__ Wq,
                                  const float* __restrict__ Wkv,
                                  const float* __restrict__ Wh)
{
    int gid = blockIdx.x * blockDim.x + threadIdx.x;
    if (gid < NI * HC) {
        int e = gid >> 9;
        int hc = gid & 511;
        int h = hc >> 7;
        int c = hc & 127;
        float s = 0.f;
#pragma unroll
        for (int d = 0; d < ND; d++)
            s += Wq[e * 128 + d * 4 + h] * Wkv[c * 640 + d * 4 + h];
        d_Mq[gid] = s * 0.17677669529663687f;   // 1/sqrt(32)
    } else {
        int g = gid - NI * HC;
        int r = g >> 7;          // h*128 + c
        int i = g & 127;
        int h = r >> 7;
        int c = r & 127;
        float s = 0.f;
#pragma unroll 8
        for (int ip = 0; ip < 128; ip++)
            s += Wkv[c * 640 + (32 + ip) * 4 + h] * Wh[(h * 128 + ip) * 128 + i];
        d_W2[g] = s;
    }
}

// ---------------- fused kernel ----------------
// smem float layout
#define OFF_GGS   0                       // 15840  (half0 rows 0-59 at 0, half1 at HALF_F)
#define OFF_QW8   (OFF_GGS + SLAB)        // 4096   (reused as epilogue partials)
#define OFF_A8T   (OFF_QW8 + 4096)        // 4096   a8t[k*8 + l]
#define OFF_SPART (OFF_A8T + 4096)        // 2048   (g1s overlaid here during prologue)
#define OFF_SWT4  (OFF_SPART + 2048)      // 512    swt4[j*4 + h]
#define OFF_SSW   (OFF_SWT4 + 512)        // 128
#define OFF_MASK  (OFF_SSW + 128)         // 128 ints
#define OFF_FLAG  (OFF_MASK + 128)        // flags
#define SMEM_FLOATS (OFF_FLAG + 8)
#define SMEM_BYTES  (SMEM_FLOATS * 4)     // ~107 KB -> 2 CTAs/SM

__device__ __forceinline__ void cp16(float* dst, const float* src)
{
    unsigned s = (unsigned)__cvta_generic_to_shared(dst);
    asm volatile("cp.async.cg.shared.global [%0], [%1], 16;\n" :: "r"(s), "l"(src));
}

// load 60-row half-slab: dstb points at half base in smem, gb at half base in gmem
__device__ __forceinline__ void issue_half(float* dstb, const float* gb, int tid)
{
#pragma unroll
    for (int w = 0; w < 4; w++) {
        int idx = tid + w * NTHR;
        if (idx < HROWS * 32) {
            int j = idx >> 5, q = idx & 31;
            cp16(dstb + j * GG_STRIDE + q * 4, gb + idx * 4);
        }
    }
    asm volatile("cp.async.commit_group;\n" ::: "memory");
}

__global__ __launch_bounds__(NTHR, 2) void fused_attn(
    const float* __restrict__ g1,
    const float* __restrict__ gg1,
    const void*  __restrict__ maskRaw,
    const float* __restrict__ sw,
    const float* __restrict__ bh,
    float* __restrict__ out)
{
    extern __shared__ float sm[];
    float* qw8    = sm + OFF_QW8;
    float* a8t    = sm + OFF_A8T;
    float* spart  = sm + OFF_SPART;
    float* g1s    = spart;                  // overlay (prologue only)
    float* swt4   = sm + OFF_SWT4;
    float* ssw    = sm + OFF_SSW;
    int*   smsk   = (int*)(sm + OFF_MASK);
    int*   sflag  = (int*)(sm + OFF_FLAG);

    const int tid = threadIdx.x;
    const int locbase = blockIdx.x * BLOC;

    if (tid == 0) { sflag[0] = 0; sflag[1] = 0; }

    // prefetch both halves of loc0's slab
    {
        const float* gb = gg1 + (size_t)locbase * (NNEI * NI);
        issue_half(sm, gb, tid);
        issue_half(sm + HALF_F, gb + HROWS * NI, tid);
    }

    // mask dtype detection from first 1KB (deterministic)
    if (tid < 64) {
        uint4 v = ((const uint4*)maskRaw)[tid];
        unsigned orw = v.x | v.y | v.z | v.w;
        if (orw & 0x00FFFF00u) atomicOr(&sflag[0], 1);
        if (orw & 0xFF000000u) atomicOr(&sflag[1], 1);
    }
    // g1 rows for the 8 locs (overlaid on spart)
    if (tid < 256) {
        int l = tid >> 5, e4 = tid & 31;
        *(float4*)&g1s[l * NI + e4 * 4] =
            *(const float4*)&g1[(size_t)(locbase + l) * NI + e4 * 4];
    }
    __syncthreads();   // B0

    // qw8[l][n] = g1[l,:] . Mq[:,n]  (n = tid) — overlaps slab prefetch
    {
        float acc[BLOC];
#pragma unroll
        for (int l = 0; l < BLOC; l++) acc[l] = 0.f;
        const float* mq = d_Mq + tid;
#pragma unroll 4
        for (int e = 0; e < NI; e++) {
            float m = mq[e * HC];
#pragma unroll
            for (int l = 0; l < BLOC; l++)
                acc[l] += g1s[l * NI + e] * m;
        }
        __syncthreads();   // done reading g1s before loop reuses spart
#pragma unroll
        for (int l = 0; l < BLOC; l++) qw8[l * HC + tid] = acc[l];
    }

    const int f12 = sflag[0], f3 = sflag[1];

    // ---------------- per-location loop ----------------
    for (int il = 0; il < BLOC; il++) {
        asm volatile("cp.async.wait_group 0;\n" ::: "memory");
        __syncthreads();   // B1: both halves of loc il resident

        // --- logits partials: thread (kq, j<120); threads j>=120 load mask/sw ---
        {
            int kq = tid >> 7, j = tid & 127;
            if (j < NNEI) {
                const float4* gr = (const float4*)(sm + j * GG_STRIDE + kq * 32);
                const float4* q0 = (const float4*)(qw8 + il * HC + 0 * NI + kq * 32);
                const float4* q1 = (const float4*)(qw8 + il * HC + 1 * NI + kq * 32);
                const float4* q2 = (const float4*)(qw8 + il * HC + 2 * NI + kq * 32);
                const float4* q3 = (const float4*)(qw8 + il * HC + 3 * NI + kq * 32);
                float p0 = 0.f, p1 = 0.f, p2 = 0.f, p3 = 0.f;
#pragma unroll
                for (int i = 0; i < 8; i++) {
                    float4 g = gr[i];
                    float4 a = q0[i]; p0 += g.x*a.x + g.y*a.y + g.z*a.z + g.w*a.w;
                    float4 b = q1[i]; p1 += g.x*b.x + g.y*b.y + g.z*b.z + g.w*b.w;
                    float4 c = q2[i]; p2 += g.x*c.x + g.y*c.y + g.z*c.z + g.w*c.w;
                    float4 d = q3[i]; p3 += g.x*d.x + g.y*d.y + g.z*d.z + g.w*d.w;
                }
                spart[kq * HC + 0 * NI + j] = p0;
                spart[kq * HC + 1 * NI + j] = p1;
                spart[kq * HC + 2 * NI + j] = p2;
                spart[kq * HC + 3 * NI + j] = p3;
            } else {
                int lid = kq * 8 + (j - NNEI);   // 0..31
                size_t base = (size_t)(locbase + il) * NNEI;
#pragma unroll
                for (int q = 0; q < 4; q++) {
                    int jj = lid + q * 32;
                    if (jj < NNEI) {
                        int m;
                        if (f12)      m = ((const unsigned char*)maskRaw)[base + jj] != 0;
                        else if (f3)  m = ((const float*)maskRaw)[base + jj] != 0.f;
                        else          m = ((const int*)maskRaw)[base + jj] != 0;
                        smsk[jj] = m;
                        ssw[jj]  = sw[base + jj];
                    }
                }
            }
        }
        __syncthreads();   // B2

        // --- masked softmax * sw (one warp per head) ---
        if (tid < 128) {
            int h = tid >> 5, lane = tid & 31;
            float lv[4]; int mk[4];
            float mx = -INFINITY;
#pragma unroll
            for (int q = 0; q < 4; q++) {
                int j = lane + q * 32;
                int in = (j < NNEI) ? smsk[j] : 0;
                float L = -INFINITY;
                if (in) L = spart[h * NI + j] + spart[HC + h * NI + j]
                          + spart[2 * HC + h * NI + j] + spart[3 * HC + h * NI + j];
                lv[q] = L; mk[q] = in;
                mx = fmaxf(mx, L);
            }
#pragma unroll
            for (int off = 16; off > 0; off >>= 1)
                mx = fmaxf(mx, __shfl_xor_sync(0xFFFFFFFFu, mx, off));
            float ev[4];
            float sum = 0.f;
#pragma unroll
            for (int q = 0; q < 4; q++) {
                ev[q] = mk[q] ? __expf(lv[q] - mx) : 0.f;
                sum += ev[q];
            }
#pragma unroll
            for (int off = 16; off > 0; off >>= 1)
                sum += __shfl_xor_sync(0xFFFFFFFFu, sum, off);
            float inv = (sum > 0.f) ? (1.f / sum) : 0.f;
#pragma unroll
            for (int q = 0; q < 4; q++) {
                int j = lane + q * 32;
                if (j < NNEI)
                    swt4[j * 4 + h] = mk[q] ? ev[q] * inv * ssw[j] : 0.f;
            }
        }
        __syncthreads();   // B3

        // --- weighted sum, half A (rows 0..59) ---
        int c = tid & 127, jq = tid >> 7;
        float s0 = 0.f, s1 = 0.f, s2 = 0.f, s3 = 0.f;
        {
            const float* gcol = sm + c;
            int j0 = jq * 15;
#pragma unroll
            for (int j = 0; j < 15; j++) {
                float g = gcol[(j0 + j) * GG_STRIDE];
                float4 w = *(const float4*)&swt4[(j0 + j) * 4];
                s0 += w.x * g; s1 += w.y * g; s2 += w.z * g; s3 += w.w * g;
            }
        }
        __syncthreads();   // B4: half-0 free
        if (il + 1 < BLOC)
            issue_half(sm, gg1 + (size_t)(locbase + il + 1) * (NNEI * NI), tid);

        // --- weighted sum, half B (rows 60..119) ---
        {
            const float* gcol = sm + c;
            int j0 = HROWS + jq * 15;
#pragma unroll
            for (int j = 0; j < 15; j++) {
                float g = gcol[(j0 + j) * GG_STRIDE];
                float4 w = *(const float4*)&swt4[(j0 + j) * 4];
                s0 += w.x * g; s1 += w.y * g; s2 += w.z * g; s3 += w.w * g;
            }
        }
        spart[jq * HC + 0 * NI + c] = s0;
        spart[jq * HC + 1 * NI + c] = s1;
        spart[jq * HC + 2 * NI + c] = s2;
        spart[jq * HC + 3 * NI + c] = s3;
        __syncthreads();   // B5: half-1 free + partials visible

        if (il + 1 < BLOC)
            issue_half(sm + HALF_F,
                       gg1 + (size_t)(locbase + il + 1) * (NNEI * NI) + HROWS * NI, tid);

        a8t[tid * 8 + il] = spart[tid] + spart[HC + tid]
                          + spart[2 * HC + tid] + spart[3 * HC + tid];
    }
    __syncthreads();

    // ---------------- fused output GEMM: out[8][128] = a[8][512] @ W2 + bh ----------------
    {
        int i = tid & 127, kq = tid >> 7;
        float acc[BLOC];
#pragma unroll
        for (int l = 0; l < BLOC; l++) acc[l] = 0.f;
        const float* w2p = d_W2 + (size_t)(kq * NI) * NI + i;
#pragma unroll 4
        for (int k = 0; k < 128; k++) {
            float w2 = w2p[k * NI];
            const float* ap = a8t + (kq * 128 + k) * 8;
            float4 lo = *(const float4*)ap;
            float4 hi = *(const float4*)(ap + 4);
            acc[0] += lo.x * w2; acc[1] += lo.y * w2;
            acc[2] += lo.z * w2; acc[3] += lo.w * w2;
            acc[4] += hi.x * w2; acc[5] += hi.y * w2;
            acc[6] += hi.z * w2; acc[7] += hi.w * w2;
        }
        __syncthreads();
#pragma unroll
        for (int l = 0; l < BLOC; l++)
            qw8[kq * 1024 + l * NI + i] = acc[l];   // reuse qw8 as epilogue partials
    }
    __syncthreads();
    for (int o = tid; o < BLOC * NI; o += NTHR) {
        int l = o >> 7, ii = o & 127;
        float v = qw8[o] + qw8[1024 + o] + qw8[2048 + o] + qw8[3072 + o] + bh[ii];
        out[(size_t)(locbase + l) * NI + ii] = v;
    }
}

// ---------------- launch ----------------
extern "C" void kernel_launch(void* const* d_in, const int* in_sizes, int n_in,
                              void* d_out, int out_size)
{
    const float* g1   = (const float*)d_in[0];
    const float* gg1  = (const float*)d_in[1];
    const void*  mask = d_in[2];
    const float* sw   = (const float*)d_in[3];
    const float* Wq   = (const float*)d_in[4];
    const float* Wkv  = (const float*)d_in[5];
    const float* Wh   = (const float*)d_in[6];
    const float* bh   = (const float*)d_in[7];
    float* out = (float*)d_out;

    int nloctot = in_sizes[0] / NI;   // 2048

    static int smem_set = 0;
    if (!smem_set) {
        cudaFuncSetAttribute(fused_attn, cudaFuncAttributeMaxDynamicSharedMemorySize, SMEM_BYTES);
        smem_set = 1;
    }

    precompute_kernel<<<512, 256>>>(Wq, Wkv, Wh);
    fused_attn<<<nloctot / BLOC, NTHR, SMEM_BYTES>>>(g1, gg1, mask, sw, bh, out);
}

// round 4
// speedup vs baseline: 1.3529x; 1.0787x over previous
#include <cuda_runtime.h>
#include <math.h>

#define NI   128
#define ND   32
#define NH   4
#define NNEI 120
#define HC   (NH * NI)   // 512
#define BLOC 8
#define NTHR 512
#define HROWS 60
#define SLABF (NNEI * NI)   // 15360 floats, XOR-swizzled, stride 128

// ---------------- scratch (device globals) ----------------
__device__ float d_Mq[NI * HC];       // 128 x 512 : combined q/k projection (incl 1/sqrt(32))
__device__ float d_W2[HC * NI];       // 512 x 128 : combined v-projection @ Wh

// ---------------- K0: precompute Mq and W2 ----------------
__global__ void precompute_kernel(const float* __restrict__ Wq,
                                  const float* __restrict__ Wkv,
                                  const float* __restrict__ Wh)
{
    int gid = blockIdx.x * blockDim.x + threadIdx.x;
    if (gid < NI * HC) {
        int e = gid >> 9;
        int hc = gid & 511;
        int h = hc >> 7;
        int c = hc & 127;
        float s = 0.f;
#pragma unroll
        for (int d = 0; d < ND; d++)
            s += Wq[e * 128 + d * 4 + h] * Wkv[c * 640 + d * 4 + h];
        d_Mq[gid] = s * 0.17677669529663687f;   // 1/sqrt(32)
    } else {
        int g = gid - NI * HC;
        int r = g >> 7;          // h*128 + c
        int i = g & 127;
        int h = r >> 7;
        int c = r & 127;
        float s = 0.f;
#pragma unroll 8
        for (int ip = 0; ip < 128; ip++)
            s += Wkv[c * 640 + (32 + ip) * 4 + h] * Wh[(h * 128 + ip) * 128 + i];
        d_W2[g] = s;
    }
}

// ---------------- fused kernel ----------------
// smem float layout
#define OFF_GGS   0                        // 15360  swizzled slab
#define OFF_QW8   (OFF_GGS + SLABF)        // 4096   (reused as epilogue partials)
#define OFF_A8T   (OFF_QW8 + 4096)         // 4096   a8t[k*8 + l]
#define OFF_SPART (OFF_A8T + 4096)         // 2048   (g1s overlaid during prologue)
#define OFF_SWT4  (OFF_SPART + 2048)       // 512    swt4[j*4 + h]
#define OFF_SSW   (OFF_SWT4 + 512)         // 128
#define OFF_MASK  (OFF_SSW + 128)          // 128 ints
#define OFF_FLAG  (OFF_MASK + 128)         // flags
#define SMEM_FLOATS (OFF_FLAG + 8)
#define SMEM_BYTES  (SMEM_FLOATS * 4)      // ~105.5 KB -> 2 CTAs/SM

__device__ __forceinline__ void cp16(float* dst, const float* src)
{
    unsigned s = (unsigned)__cvta_generic_to_shared(dst);
    asm volatile("cp.async.cg.shared.global [%0], [%1], 16;\n" :: "r"(s), "l"(src));
}

// load one 60-row half-slab into the XOR-swizzled layout; one commit group
__device__ __forceinline__ void issue_half(float* slab, int halfsel,
                                           const float* gslab, int tid)
{
    const int jbase = halfsel * HROWS;
    const float* gb = gslab + jbase * NI;
#pragma unroll
    for (int w = 0; w < 4; w++) {
        int idx = tid + w * NTHR;
        if (idx < HROWS * 32) {
            int j = idx >> 5, q = idx & 31;
            int jj = jbase + j;
            cp16(slab + jj * NI + ((q ^ (jj & 7)) << 2), gb + idx * 4);
        }
    }
    asm volatile("cp.async.commit_group;\n" ::: "memory");
}

__global__ __launch_bounds__(NTHR, 2) void fused_attn(
    const float* __restrict__ g1,
    const float* __restrict__ gg1,
    const void*  __restrict__ maskRaw,
    const float* __restrict__ sw,
    const float* __restrict__ bh,
    float* __restrict__ out)
{
    extern __shared__ float sm[];
    float* qw8    = sm + OFF_QW8;
    float* a8t    = sm + OFF_A8T;
    float* spart  = sm + OFF_SPART;
    float* g1s    = spart;                  // overlay (prologue only)
    float* swt4   = sm + OFF_SWT4;
    float* ssw    = sm + OFF_SSW;
    int*   smsk   = (int*)(sm + OFF_MASK);
    int*   sflag  = (int*)(sm + OFF_FLAG);

    const int tid = threadIdx.x;
    const int locbase = blockIdx.x * BLOC;

    if (tid == 0) { sflag[0] = 0; sflag[1] = 0; }

    // prefetch both halves of loc0's slab (2 commit groups)
    {
        const float* gslab = gg1 + (size_t)locbase * SLABF;
        issue_half(sm, 0, gslab, tid);
        issue_half(sm, 1, gslab, tid);
    }

    // mask dtype detection from first 1KB (deterministic)
    if (tid < 64) {
        uint4 v = ((const uint4*)maskRaw)[tid];
        unsigned orw = v.x | v.y | v.z | v.w;
        if (orw & 0x00FFFF00u) atomicOr(&sflag[0], 1);
        if (orw & 0xFF000000u) atomicOr(&sflag[1], 1);
    }
    // g1 rows for the 8 locs (overlaid on spart)
    if (tid < 256) {
        int l = tid >> 5, e4 = tid & 31;
        *(float4*)&g1s[l * NI + e4 * 4] =
            *(const float4*)&g1[(size_t)(locbase + l) * NI + e4 * 4];
    }
    __syncthreads();

    // qw8[l][n] = g1[l,:] . Mq[:,n]  — overlaps loc0 slab prefetch
    {
        float acc[BLOC];
#pragma unroll
        for (int l = 0; l < BLOC; l++) acc[l] = 0.f;
        const float* mq = d_Mq + tid;
#pragma unroll 8
        for (int e = 0; e < NI; e++) {
            float m = mq[e * HC];
#pragma unroll
            for (int l = 0; l < BLOC; l++)
                acc[l] += g1s[l * NI + e] * m;
        }
        __syncthreads();   // g1s reads done before spart reuse
#pragma unroll
        for (int l = 0; l < BLOC; l++) qw8[l * HC + tid] = acc[l];
    }

    const int f12 = sflag[0], f3 = sflag[1];
    const int kq = tid >> 7;
    const int jt = tid & 127;

    // ---------------- per-location loop ----------------
    for (int il = 0; il < BLOC; il++) {
        // ---- half A resident ----
        asm volatile("cp.async.wait_group 1;\n" ::: "memory");
        __syncthreads();

        // logits pass A: rows 0..59 ; threads jt>=120 load mask/sw
        if (jt < HROWS) {
            const float* gr = sm + jt * NI + kq * 32;
            const int jm = jt & 7;
            const float4* q0 = (const float4*)(qw8 + il * HC + 0 * NI + kq * 32);
            const float4* q1 = (const float4*)(qw8 + il * HC + 1 * NI + kq * 32);
            const float4* q2 = (const float4*)(qw8 + il * HC + 2 * NI + kq * 32);
            const float4* q3 = (const float4*)(qw8 + il * HC + 3 * NI + kq * 32);
            float p0 = 0.f, p1 = 0.f, p2 = 0.f, p3 = 0.f;
#pragma unroll
            for (int i = 0; i < 8; i++) {
                float4 g = *(const float4*)(gr + ((i ^ jm) << 2));
                float4 a = q0[i]; p0 += g.x*a.x + g.y*a.y + g.z*a.z + g.w*a.w;
                float4 b = q1[i]; p1 += g.x*b.x + g.y*b.y + g.z*b.z + g.w*b.w;
                float4 c = q2[i]; p2 += g.x*c.x + g.y*c.y + g.z*c.z + g.w*c.w;
                float4 d = q3[i]; p3 += g.x*d.x + g.y*d.y + g.z*d.z + g.w*d.w;
            }
            spart[kq * HC + 0 * NI + jt] = p0;
            spart[kq * HC + 1 * NI + jt] = p1;
            spart[kq * HC + 2 * NI + jt] = p2;
            spart[kq * HC + 3 * NI + jt] = p3;
        } else if (jt >= 120) {
            int lid = kq * 8 + (jt - 120);   // 0..31
            size_t base = (size_t)(locbase + il) * NNEI;
#pragma unroll
            for (int q = 0; q < 4; q++) {
                int jj = lid + q * 32;
                if (jj < NNEI) {
                    int m;
                    if (f12)      m = ((const unsigned char*)maskRaw)[base + jj] != 0;
                    else if (f3)  m = ((const float*)maskRaw)[base + jj] != 0.f;
                    else          m = ((const int*)maskRaw)[base + jj] != 0;
                    smsk[jj] = m;
                    ssw[jj]  = sw[base + jj];
                }
            }
        }

        // ---- half B resident ----
        asm volatile("cp.async.wait_group 0;\n" ::: "memory");
        __syncthreads();

        // logits pass B: rows 60..119
        if (jt >= HROWS && jt < NNEI) {
            const float* gr = sm + jt * NI + kq * 32;
            const int jm = jt & 7;
            const float4* q0 = (const float4*)(qw8 + il * HC + 0 * NI + kq * 32);
            const float4* q1 = (const float4*)(qw8 + il * HC + 1 * NI + kq * 32);
            const float4* q2 = (const float4*)(qw8 + il * HC + 2 * NI + kq * 32);
            const float4* q3 = (const float4*)(qw8 + il * HC + 3 * NI + kq * 32);
            float p0 = 0.f, p1 = 0.f, p2 = 0.f, p3 = 0.f;
#pragma unroll
            for (int i = 0; i < 8; i++) {
                float4 g = *(const float4*)(gr + ((i ^ jm) << 2));
                float4 a = q0[i]; p0 += g.x*a.x + g.y*a.y + g.z*a.z + g.w*a.w;
                float4 b = q1[i]; p1 += g.x*b.x + g.y*b.y + g.z*b.z + g.w*b.w;
                float4 c = q2[i]; p2 += g.x*c.x + g.y*c.y + g.z*c.z + g.w*c.w;
                float4 d = q3[i]; p3 += g.x*d.x + g.y*d.y + g.z*d.z + g.w*d.w;
            }
            spart[kq * HC + 0 * NI + jt] = p0;
            spart[kq * HC + 1 * NI + jt] = p1;
            spart[kq * HC + 2 * NI + jt] = p2;
            spart[kq * HC + 3 * NI + jt] = p3;
        }
        __syncthreads();

        // --- masked softmax * sw (one warp per head) ---
        if (tid < 128) {
            int h = tid >> 5, lane = tid & 31;
            float lv[4]; int mk[4];
            float mx = -INFINITY;
#pragma unroll
            for (int q = 0; q < 4; q++) {
                int j = lane + q * 32;
                int in = (j < NNEI) ? smsk[j] : 0;
                float L = -INFINITY;
                if (in) L = spart[h * NI + j] + spart[HC + h * NI + j]
                          + spart[2 * HC + h * NI + j] + spart[3 * HC + h * NI + j];
                lv[q] = L; mk[q] = in;
                mx = fmaxf(mx, L);
            }
#pragma unroll
            for (int off = 16; off > 0; off >>= 1)
                mx = fmaxf(mx, __shfl_xor_sync(0xFFFFFFFFu, mx, off));
            float ev[4];
            float sum = 0.f;
#pragma unroll
            for (int q = 0; q < 4; q++) {
                ev[q] = mk[q] ? __expf(lv[q] - mx) : 0.f;
                sum += ev[q];
            }
#pragma unroll
            for (int off = 16; off > 0; off >>= 1)
                sum += __shfl_xor_sync(0xFFFFFFFFu, sum, off);
            float inv = (sum > 0.f) ? (1.f / sum) : 0.f;
#pragma unroll
            for (int q = 0; q < 4; q++) {
                int j = lane + q * 32;
                if (j < NNEI)
                    swt4[j * 4 + h] = mk[q] ? ev[q] * inv * ssw[j] : 0.f;
            }
        }
        __syncthreads();

        // --- weighted sum (strided-j partition so swizzle offset alternates) ---
        const int c = jt;            // 0..127
        const int jq = kq;           // 0..3
        const int c4 = c >> 2, co = c & 3;
        const int off0 = ((c4 ^ jq) << 2) + co;
        const int off1 = off0 ^ 16;
        float s0 = 0.f, s1 = 0.f, s2 = 0.f, s3 = 0.f;

        // half A: j = jq + 4t
#pragma unroll
        for (int t = 0; t < 15; t++) {
            int j = jq + 4 * t;
            float g = sm[j * NI + ((t & 1) ? off1 : off0)];
            float4 w = *(const float4*)&swt4[j * 4];
            s0 += w.x * g; s1 += w.y * g; s2 += w.z * g; s3 += w.w * g;
        }
        __syncthreads();   // half A free
        if (il + 1 < BLOC)
            issue_half(sm, 0, gg1 + (size_t)(locbase + il + 1) * SLABF, tid);

        // half B: j = 60 + jq + 4t  (swizzle parity flipped: 60&7 == 4)
#pragma unroll
        for (int t = 0; t < 15; t++) {
            int j = HROWS + jq + 4 * t;
            float g = sm[j * NI + ((t & 1) ? off0 : off1)];
            float4 w = *(const float4*)&swt4[j * 4];
            s0 += w.x * g; s1 += w.y * g; s2 += w.z * g; s3 += w.w * g;
        }
        spart[jq * HC + 0 * NI + c] = s0;
        spart[jq * HC + 1 * NI + c] = s1;
        spart[jq * HC + 2 * NI + c] = s2;
        spart[jq * HC + 3 * NI + c] = s3;
        __syncthreads();   // half B free + partials visible

        if (il + 1 < BLOC)
            issue_half(sm, 1, gg1 + (size_t)(locbase + il + 1) * SLABF, tid);

        a8t[tid * 8 + il] = spart[tid] + spart[HC + tid]
                          + spart[2 * HC + tid] + spart[3 * HC + tid];
    }
    __syncthreads();

    // ---------------- fused output GEMM: out[8][128] = a[8][512] @ W2 + bh ----------------
    {
        int i = tid & 127, kq2 = tid >> 7;
        float acc[BLOC];
#pragma unroll
        for (int l = 0; l < BLOC; l++) acc[l] = 0.f;
        const float* w2p = d_W2 + (size_t)(kq2 * NI) * NI + i;
#pragma unroll 4
        for (int k = 0; k < 128; k++) {
            float w2 = w2p[k * NI];
            const float* ap = a8t + (kq2 * 128 + k) * 8;
            float4 lo = *(const float4*)ap;
            float4 hi = *(const float4*)(ap + 4);
            acc[0] += lo.x * w2; acc[1] += lo.y * w2;
            acc[2] += lo.z * w2; acc[3] += lo.w * w2;
            acc[4] += hi.x * w2; acc[5] += hi.y * w2;
            acc[6] += hi.z * w2; acc[7] += hi.w * w2;
        }
        __syncthreads();
#pragma unroll
        for (int l = 0; l < BLOC; l++)
            qw8[kq2 * 1024 + l * NI + i] = acc[l];   // reuse qw8 as epilogue partials
    }
    __syncthreads();
    for (int o = tid; o < BLOC * NI; o += NTHR) {
        int l = o >> 7, ii = o & 127;
        float v = qw8[o] + qw8[1024 + o] + qw8[2048 + o] + qw8[3072 + o] + bh[ii];
        out[(size_t)(locbase + l) * NI + ii] = v;
    }
}

// ---------------- launch ----------------
extern "C" void kernel_launch(void* const* d_in, const int* in_sizes, int n_in,
                              void* d_out, int out_size)
{
    const float* g1   = (const float*)d_in[0];
    const float* gg1  = (const float*)d_in[1];
    const void*  mask = d_in[2];
    const float* sw   = (const float*)d_in[3];
    const float* Wq   = (const float*)d_in[4];
    const float* Wkv  = (const float*)d_in[5];
    const float* Wh   = (const float*)d_in[6];
    const float* bh   = (const float*)d_in[7];
    float* out = (float*)d_out;

    int nloctot = in_sizes[0] / NI;   // 2048

    static int smem_set = 0;
    if (!smem_set) {
        cudaFuncSetAttribute(fused_attn, cudaFuncAttributeMaxDynamicSharedMemorySize, SMEM_BYTES);
        smem_set = 1;
    }

    precompute_kernel<<<512, 256>>>(Wq, Wkv, Wh);
    fused_attn<<<nloctot / BLOC, NTHR, SMEM_BYTES>>>(g1, gg1, mask, sw, bh, out);
}

// round 6
// speedup vs baseline: 1.5323x; 1.1325x over previous
#include <cuda_runtime.h>
#include <math.h>

#define NI   128
#define ND   32
#define NH   4
#define NNEI 120
#define HC   (NH * NI)   // 512
#define BLOC 7
#define NTHR 512
#define HROWS 60
#define SLABF (NNEI * NI)   // 15360 floats, XOR-swizzled, stride 128

// ---------------- scratch (device globals) ----------------
__device__ float d_Mq[NI * HC];       // 128 x 512 : combined q/k projection (incl 1/sqrt(32))
__device__ float d_W2[HC * NI];       // 512 x 128 : combined v-projection @ Wh

// ---------------- K0: precompute Mq and W2 ----------------
__global__ void precompute_kernel(const float* __restrict__ Wq,
                                  const float* __restrict__ Wkv,
                                  const float* __restrict__ Wh)
{
    int gid = blockIdx.x * blockDim.x + threadIdx.x;
    if (gid < NI * HC) {
        int e = gid >> 9;
        int hc = gid & 511;
        int h = hc >> 7;
        int c = hc & 127;
        float s = 0.f;
#pragma unroll
        for (int d = 0; d < ND; d++)
            s += Wq[e * 128 + d * 4 + h] * Wkv[c * 640 + d * 4 + h];
        d_Mq[gid] = s * 0.17677669529663687f;   // 1/sqrt(32)
    } else {
        int g = gid - NI * HC;
        int r = g >> 7;          // h*128 + c
        int i = g & 127;
        int h = r >> 7;
        int c = r & 127;
        float s = 0.f;
#pragma unroll 8
        for (int ip = 0; ip < 128; ip++)
            s += Wkv[c * 640 + (32 + ip) * 4 + h] * Wh[(h * 128 + ip) * 128 + i];
        d_W2[g] = s;
    }
}

// ---------------- smem float layout ----------------
#define OFF_GGS   0                        // 15360 swizzled slab
#define OFF_QW8   (OFF_GGS + SLABF)        // 4096  qw (reused as epilogue partials)
#define OFF_A8T   (OFF_QW8 + 4096)         // 4096  a8t[k*8 + l]
#define OFF_SPART (OFF_A8T + 4096)         // 2048  (g1s + mask-stage overlaid in prologue)
#define OFF_SWT4  (OFF_SPART + 2048)       // 512   swt4[j*4 + h]
#define OFF_SSW   (OFF_SWT4 + 512)         // 848   ssw8[il*120 + j]
#define OFF_MASK  (OFF_SSW + 848)          // 848   smsk8[il*120 + j] (ints)
#define OFF_FLAG  (OFF_MASK + 848)         // flags
#define SMEM_FLOATS (OFF_FLAG + 8)
#define SMEM_BYTES  (SMEM_FLOATS * 4)      // ~111.3 KB -> 2 CTAs/SM

__device__ __forceinline__ void cp16(void* dst, const void* src)
{
    unsigned s = (unsigned)__cvta_generic_to_shared(dst);
    asm volatile("cp.async.cg.shared.global [%0], [%1], 16;\n" :: "r"(s), "l"(src));
}
__device__ __forceinline__ void cp8(void* dst, const void* src)
{
    unsigned s = (unsigned)__cvta_generic_to_shared(dst);
    asm volatile("cp.async.ca.shared.global [%0], [%1], 8;\n" :: "r"(s), "l"(src));
}

// load one 60-row half-slab into the XOR-swizzled layout; one commit group
template<int STRIDE>
__device__ __forceinline__ void issue_half(float* slab, int halfsel,
                                           const float* gslab, int t)
{
    const int jbase = halfsel * HROWS;
    const float* gb = gslab + jbase * NI;
#pragma unroll
    for (int w = 0; w < (HROWS * 32 + STRIDE - 1) / STRIDE; w++) {
        int idx = t + w * STRIDE;
        if (idx < HROWS * 32) {
            int j = idx >> 5, q = idx & 31;
            int jj = jbase + j;
            cp16(slab + jj * NI + ((q ^ (jj & 7)) << 2), gb + idx * 4);
        }
    }
    asm volatile("cp.async.commit_group;\n" ::: "memory");
}

__global__ __launch_bounds__(NTHR, 2) void fused_attn(
    const float* __restrict__ g1,
    const float* __restrict__ gg1,
    const void*  __restrict__ maskRaw,
    const float* __restrict__ sw,
    const float* __restrict__ bh,
    float* __restrict__ out,
    int nloctot)
{
    extern __shared__ float sm[];
    float* qw8    = sm + OFF_QW8;
    float* a8t    = sm + OFF_A8T;
    float* spart  = sm + OFF_SPART;
    float* g1s    = spart;                  // prologue overlay [0..896)
    int*   mtmp   = (int*)(spart + 1024);   // prologue overlay [1024..1864)
    float* swt4   = sm + OFF_SWT4;
    float* ssw8   = sm + OFF_SSW;
    int*   smsk8  = (int*)(sm + OFF_MASK);
    int*   sflag  = (int*)(sm + OFF_FLAG);

    const int tid = threadIdx.x;
    const int locbase = blockIdx.x * BLOC;
    const int count = min(BLOC, nloctot - locbase);
    if (count <= 0) return;

    if (tid == 0) { sflag[0] = 0; sflag[1] = 0; }

    // prefetch both halves of loc0's slab (groups 0,1)
    {
        const float* gslab = gg1 + (size_t)locbase * SLABF;
        issue_half<NTHR>(sm, 0, gslab, tid);
        issue_half<NTHR>(sm, 1, gslab, tid);
    }

    // mask dtype detection from first 1KB (deterministic)
    if (tid < 64) {
        uint4 v = ((const uint4*)maskRaw)[tid];
        unsigned orw = v.x | v.y | v.z | v.w;
        if (orw & 0x00FFFF00u) atomicOr(&sflag[0], 1);
        if (orw & 0xFF000000u) atomicOr(&sflag[1], 1);
    }
    // g1 rows for the block's locs
    if (tid < 32 * BLOC) {
        int l = tid >> 5, e4 = tid & 31;
        if (l < count)
            *(float4*)&g1s[l * NI + e4 * 4] =
                *(const float4*)&g1[(size_t)(locbase + l) * NI + e4 * 4];
    }
    __syncthreads();   // B0: flags + g1s visible

    const int f12 = sflag[0], f3 = sflag[1];
    const int nel = count * NNEI;

    // stage sw + raw mask via cp.async (group 2) — overlaps qw projection
    {
        const float* swsrc = sw + (size_t)locbase * NNEI;
        for (int t2 = tid; t2 < (nel >> 2); t2 += NTHR)
            cp16(ssw8 + t2 * 4, swsrc + t2 * 4);
        if (f12) {          // 1-byte mask
            const char* mb = (const char*)maskRaw + (size_t)locbase * NNEI;
            for (int t2 = tid; t2 < (nel >> 3); t2 += NTHR)
                cp8((char*)mtmp + t2 * 8, mb + t2 * 8);
        } else {            // 4-byte mask (int or float)
            const char* mb = (const char*)maskRaw + (size_t)locbase * NNEI * 4;
            for (int t2 = tid; t2 < (nel >> 2); t2 += NTHR)
                cp16((char*)mtmp + t2 * 16, mb + t2 * 16);
        }
        asm volatile("cp.async.commit_group;\n" ::: "memory");
    }

    // qw[l][n] = g1[l,:] . Mq[:,n]  (n = tid) — overlaps slab + staging
    {
        float acc[BLOC];
#pragma unroll
        for (int l = 0; l < BLOC; l++) acc[l] = 0.f;
        const float* mq = d_Mq + tid;
#pragma unroll 8
        for (int e = 0; e < NI; e++) {
            float m = mq[e * HC];
#pragma unroll
            for (int l = 0; l < BLOC; l++)
                acc[l] += g1s[l * NI + e] * m;
        }
        __syncthreads();   // B1: g1s reads done
#pragma unroll
        for (int l = 0; l < BLOC; l++) qw8[l * HC + tid] = acc[l];
    }

    // staged data ready -> convert mask
    asm volatile("cp.async.wait_group 0;\n" ::: "memory");
    __syncthreads();       // B2: staged bytes visible to all
    for (int t2 = tid; t2 < nel; t2 += NTHR) {
        int m;
        if (f12)      m = ((const unsigned char*)mtmp)[t2] != 0;
        else if (f3)  m = ((const float*)mtmp)[t2] != 0.f;
        else          m = mtmp[t2] != 0;
        smsk8[t2] = m;
    }
    __syncthreads();       // B3: smsk8 done; spart (mtmp) free for logits

    // SMSP-balanced logits mapping
    const int wid = tid >> 5, lane = tid & 31;
    const int kq = wid & 3;                    // k-quarter: same for all lanes of a warp
    const int jt = ((wid >> 2) << 5) + lane;   // 0..127, warps span all SMSP residues
    const int cw = tid & 127;                  // wsum column
    const int gw = tid >> 7;                   // wsum row-group (30 rows each)
    const int c4 = cw >> 2, co = cw & 3;

    // ---------------- per-location loop ----------------
    for (int il = 0; il < count; il++) {
        asm volatile("cp.async.wait_group 1;\n" ::: "memory");
        __syncthreads();   // half A resident

        // logits pass A: rows 0..59
        if (jt < HROWS) {
            const float* gr = sm + jt * NI + kq * 32;
            const int jm = jt & 7;
            const float4* q0 = (const float4*)(qw8 + il * HC + 0 * NI + kq * 32);
            const float4* q1 = (const float4*)(qw8 + il * HC + 1 * NI + kq * 32);
            const float4* q2 = (const float4*)(qw8 + il * HC + 2 * NI + kq * 32);
            const float4* q3 = (const float4*)(qw8 + il * HC + 3 * NI + kq * 32);
            float p0 = 0.f, p1 = 0.f, p2 = 0.f, p3 = 0.f;
#pragma unroll
            for (int i = 0; i < 8; i++) {
                float4 g = *(const float4*)(gr + ((i ^ jm) << 2));
                float4 a = q0[i]; p0 += g.x*a.x + g.y*a.y + g.z*a.z + g.w*a.w;
                float4 b = q1[i]; p1 += g.x*b.x + g.y*b.y + g.z*b.z + g.w*b.w;
                float4 c = q2[i]; p2 += g.x*c.x + g.y*c.y + g.z*c.z + g.w*c.w;
                float4 d = q3[i]; p3 += g.x*d.x + g.y*d.y + g.z*d.z + g.w*d.w;
            }
            spart[kq * HC + 0 * NI + jt] = p0;
            spart[kq * HC + 1 * NI + jt] = p1;
            spart[kq * HC + 2 * NI + jt] = p2;
            spart[kq * HC + 3 * NI + jt] = p3;
        }

        asm volatile("cp.async.wait_group 0;\n" ::: "memory");
        __syncthreads();   // half B resident

        // logits pass B: rows 60..119
        if (jt >= HROWS && jt < NNEI) {
            const float* gr = sm + jt * NI + kq * 32;
            const int jm = jt & 7;
            const float4* q0 = (const float4*)(qw8 + il * HC + 0 * NI + kq * 32);
            const float4* q1 = (const float4*)(qw8 + il * HC + 1 * NI + kq * 32);
            const float4* q2 = (const float4*)(qw8 + il * HC + 2 * NI + kq * 32);
            const float4* q3 = (const float4*)(qw8 + il * HC + 3 * NI + kq * 32);
            float p0 = 0.f, p1 = 0.f, p2 = 0.f, p3 = 0.f;
#pragma unroll
            for (int i = 0; i < 8; i++) {
                float4 g = *(const float4*)(gr + ((i ^ jm) << 2));
                float4 a = q0[i]; p0 += g.x*a.x + g.y*a.y + g.z*a.z + g.w*a.w;
                float4 b = q1[i]; p1 += g.x*b.x + g.y*b.y + g.z*b.z + g.w*b.w;
                float4 c = q2[i]; p2 += g.x*c.x + g.y*c.y + g.z*c.z + g.w*c.w;
                float4 d = q3[i]; p3 += g.x*d.x + g.y*d.y + g.z*d.z + g.w*d.w;
            }
            spart[kq * HC + 0 * NI + jt] = p0;
            spart[kq * HC + 1 * NI + jt] = p1;
            spart[kq * HC + 2 * NI + jt] = p2;
            spart[kq * HC + 3 * NI + jt] = p3;
        }
        __syncthreads();

        // --- masked softmax * sw (one warp per head) ---
        if (tid < 128) {
            int h = tid >> 5, ln = tid & 31;
            float lv[4]; int mk[4];
            float mx = -INFINITY;
#pragma unroll
            for (int q = 0; q < 4; q++) {
                int j = ln + q * 32;
                int in = (j < NNEI) ? smsk8[il * NNEI + j] : 0;
                float L = -INFINITY;
                if (in) L = spart[h * NI + j] + spart[HC + h * NI + j]
                          + spart[2 * HC + h * NI + j] + spart[3 * HC + h * NI + j];
                lv[q] = L; mk[q] = in;
                mx = fmaxf(mx, L);
            }
#pragma unroll
            for (int off = 16; off > 0; off >>= 1)
                mx = fmaxf(mx, __shfl_xor_sync(0xFFFFFFFFu, mx, off));
            float ev[4];
            float sum = 0.f;
#pragma unroll
            for (int q = 0; q < 4; q++) {
                ev[q] = mk[q] ? __expf(lv[q] - mx) : 0.f;
                sum += ev[q];
            }
#pragma unroll
            for (int off = 16; off > 0; off >>= 1)
                sum += __shfl_xor_sync(0xFFFFFFFFu, sum, off);
            float inv = (sum > 0.f) ? (1.f / sum) : 0.f;
#pragma unroll
            for (int q = 0; q < 4; q++) {
                int j = ln + q * 32;
                if (j < NNEI)
                    swt4[j * 4 + h] = mk[q] ? ev[q] * inv * ssw8[il * NNEI + j] : 0.f;
            }
        }
        __syncthreads();

        // --- weighted sum: group gw owns rows [30*gw, 30*gw+30) ---
        {
            float s0 = 0.f, s1 = 0.f, s2 = 0.f, s3 = 0.f;
            int j0 = gw * 30;
#pragma unroll
            for (int t = 0; t < 30; t++) {
                int j = j0 + t;
                float g = sm[j * NI + (((c4 ^ (j & 7)) << 2) | co)];
                float4 w = *(const float4*)&swt4[j * 4];
                s0 += w.x * g; s1 += w.y * g; s2 += w.z * g; s3 += w.w * g;
            }
            spart[gw * HC + 0 * NI + cw] = s0;
            spart[gw * HC + 1 * NI + cw] = s1;
            spart[gw * HC + 2 * NI + cw] = s2;
            spart[gw * HC + 3 * NI + cw] = s3;
        }

        // warps 0-7 (rows 0..59 readers) sync among themselves, then start A'
        if (tid < 256) {
            asm volatile("bar.sync 1, 256;" ::: "memory");
            if (il + 1 < count)
                issue_half<256>(sm, 0, gg1 + (size_t)(locbase + il + 1) * SLABF, tid);
        }
        __syncthreads();   // B5: partials visible, half B free

        if (il + 1 < count)
            issue_half<NTHR>(sm, 1, gg1 + (size_t)(locbase + il + 1) * SLABF, tid);

        a8t[(tid << 3) + il] = spart[tid] + spart[HC + tid]
                             + spart[2 * HC + tid] + spart[3 * HC + tid];
    }
    __syncthreads();

    // ---------------- fused output GEMM: out[l][128] = a[l][512] @ W2 + bh ----------------
    {
        int i = tid & 127, kq2 = tid >> 7;
        float acc[BLOC];
#pragma unroll
        for (int l = 0; l < BLOC; l++) acc[l] = 0.f;
        const float* w2p = d_W2 + (size_t)(kq2 * NI) * NI + i;
#pragma unroll 8
        for (int k = 0; k < 128; k++) {
            float w2 = w2p[k * NI];
            const float* ap = a8t + ((kq2 * 128 + k) << 3);
            float4 lo = *(const float4*)ap;
            float4 hi = *(const float4*)(ap + 4);
            acc[0] += lo.x * w2; acc[1] += lo.y * w2;
            acc[2] += lo.z * w2; acc[3] += lo.w * w2;
            acc[4] += hi.x * w2; acc[5] += hi.y * w2;
            acc[6] += hi.z * w2;
        }
        __syncthreads();
#pragma unroll
        for (int l = 0; l < BLOC; l++)
            qw8[kq2 * 1024 + l * NI + i] = acc[l];   // reuse qw8 as epilogue partials
    }
    __syncthreads();
    for (int o = tid; o < BLOC * NI; o += NTHR) {
        int l = o >> 7, ii = o & 127;
        if (l < count) {
            float v = qw8[l * NI + ii] + qw8[1024 + l * NI + ii]
                    + qw8[2048 + l * NI + ii] + qw8[3072 + l * NI + ii] + bh[ii];
            out[(size_t)(locbase + l) * NI + ii] = v;
        }
    }
}

// ---------------- launch ----------------
extern "C" void kernel_launch(void* const* d_in, const int* in_sizes, int n_in,
                              void* d_out, int out_size)
{
    const float* g1   = (const float*)d_in[0];
    const float* gg1  = (const float*)d_in[1];
    const void*  mask = d_in[2];
    const float* sw   = (const float*)d_in[3];
    const float* Wq   = (const float*)d_in[4];
    const float* Wkv  = (const float*)d_in[5];
    const float* Wh   = (const float*)d_in[6];
    const float* bh   = (const float*)d_in[7];
    float* out = (float*)d_out;

    int nloctot = in_sizes[0] / NI;   // 2048

    static int smem_set = 0;
    if (!smem_set) {
        cudaFuncSetAttribute(fused_attn, cudaFuncAttributeMaxDynamicSharedMemorySize, SMEM_BYTES);
        smem_set = 1;
    }

    int grid = (nloctot + BLOC - 1) / BLOC;   // 293

    precompute_kernel<<<512, 256>>>(Wq, Wkv, Wh);
    fused_attn<<<grid, NTHR, SMEM_BYTES>>>(g1, gg1, mask, sw, bh, out, nloctot);
}

// round 7
// speedup vs baseline: 1.5699x; 1.0245x over previous
#include <cuda_runtime.h>
#include <math.h>

#define NI   128
#define ND   32
#define NH   4
#define NNEI 120
#define HC   (NH * NI)   // 512
#define BLOC 14
#define NTHR 512
#define SLABF (NNEI * NI)   // 15360 floats, XOR-swizzled, stride 128

// ---------------- scratch (device globals) ----------------
__device__ float d_Mq[NI * HC];       // 128 x 512 : combined q/k projection (incl 1/sqrt(32))
__device__ float d_W2[HC * NI];       // 512 x 128 : combined v-projection @ Wh

// ---------------- K0: precompute Mq and W2 ----------------
__global__ void precompute_kernel(const float* __restrict__ Wq,
                                  const float* __restrict__ Wkv,
                                  const float* __restrict__ Wh)
{
    int gid = blockIdx.x * blockDim.x + threadIdx.x;
    if (gid < NI * HC) {
        int e = gid >> 9;
        int hc = gid & 511;
        int h = hc >> 7;
        int c = hc & 127;
        float s = 0.f;
#pragma unroll
        for (int d = 0; d < ND; d++)
            s += Wq[e * 128 + d * 4 + h] * Wkv[c * 640 + d * 4 + h];
        d_Mq[gid] = s * 0.17677669529663687f;   // 1/sqrt(32)
    } else {
        int g = gid - NI * HC;
        int r = g >> 7;          // h*128 + c
        int i = g & 127;
        int h = r >> 7;
        int c = r & 127;
        float s = 0.f;
#pragma unroll 8
        for (int ip = 0; ip < 128; ip++)
            s += Wkv[c * 640 + (32 + ip) * 4 + h] * Wh[(h * 128 + ip) * 128 + i];
        d_W2[g] = s;
    }
}

// ---------------- smem float layout (all 16B-aligned) ----------------
#define OFF_SLAB0 0                        // 15360
#define OFF_SLAB1 15360                    // 15360
#define OFF_QW    30720                    // 7168 = BLOC*512  (reused as epilogue partials: 4*BLOC*128)
#define OFF_A8T   37888                    // 8192 = 512*16  a8t[hc][l], stride 16 (g1s overlaid in prologue)
#define OFF_SPART 46080                    // 2048  (mtmp overlaid in prologue)
#define OFF_SWT4  48128                    // 512   swt4[j*4 + h]
#define OFF_SSW   48640                    // 1696  ssw8[il*120 + j]
#define OFF_MASK  50336                    // 1696  smsk8[il*120 + j] (ints)
#define OFF_FLAG  52032                    // flags
#define SMEM_FLOATS (OFF_FLAG + 8)
#define SMEM_BYTES  (SMEM_FLOATS * 4)      // ~208 KB -> 1 CTA/SM

__device__ __forceinline__ void cp16(void* dst, const void* src)
{
    unsigned s = (unsigned)__cvta_generic_to_shared(dst);
    asm volatile("cp.async.cg.shared.global [%0], [%1], 16;\n" :: "r"(s), "l"(src));
}
__device__ __forceinline__ void cp8(void* dst, const void* src)
{
    unsigned s = (unsigned)__cvta_generic_to_shared(dst);
    asm volatile("cp.async.ca.shared.global [%0], [%1], 8;\n" :: "r"(s), "l"(src));
}

// full 120-row slab into XOR-swizzled layout; one commit group
__device__ __forceinline__ void issue_slab(float* dst, const float* gsrc, int tid)
{
#pragma unroll
    for (int w = 0; w < 8; w++) {
        int idx = tid + w * NTHR;
        if (idx < SLABF / 4) {
            int j = idx >> 5, q = idx & 31;
            cp16(dst + j * NI + ((q ^ (j & 7)) << 2), gsrc + idx * 4);
        }
    }
    asm volatile("cp.async.commit_group;\n" ::: "memory");
}

__global__ __launch_bounds__(NTHR, 1) void fused_attn(
    const float* __restrict__ g1,
    const float* __restrict__ gg1,
    const void*  __restrict__ maskRaw,
    const float* __restrict__ sw,
    const float* __restrict__ bh,
    float* __restrict__ out,
    int nloctot)
{
    extern __shared__ float sm[];
    float* qw     = sm + OFF_QW;
    float* a8t    = sm + OFF_A8T;
    float* g1s    = a8t;                    // prologue overlay (BLOC*128 <= 8192)
    float* spart  = sm + OFF_SPART;
    int*   mtmp   = (int*)spart;            // prologue overlay (<=1680 ints)
    float* swt4   = sm + OFF_SWT4;
    float* ssw8   = sm + OFF_SSW;
    int*   smsk8  = (int*)(sm + OFF_MASK);
    int*   sflag  = (int*)(sm + OFF_FLAG);

    const int tid = threadIdx.x;
    const int locbase = blockIdx.x * BLOC;
    const int count = min(BLOC, nloctot - locbase);
    if (count <= 0) return;

    if (tid == 0) { sflag[0] = 0; sflag[1] = 0; }

    // prefetch slabs for loc0 (g0) and loc1 (g1grp)
    issue_slab(sm + OFF_SLAB0, gg1 + (size_t)locbase * SLABF, tid);
    issue_slab(sm + OFF_SLAB1,
               gg1 + (size_t)(locbase + (count > 1 ? 1 : 0)) * SLABF, tid);

    // mask dtype detection from first 1KB (deterministic)
    if (tid < 64) {
        uint4 v = ((const uint4*)maskRaw)[tid];
        unsigned orw = v.x | v.y | v.z | v.w;
        if (orw & 0x00FFFF00u) atomicOr(&sflag[0], 1);
        if (orw & 0xFF000000u) atomicOr(&sflag[1], 1);
    }
    // g1 rows (overlaid on a8t)
    if (tid < 32 * BLOC) {
        int l = tid >> 5, e4 = tid & 31;
        if (l < count)
            *(float4*)&g1s[l * NI + e4 * 4] =
                *(const float4*)&g1[(size_t)(locbase + l) * NI + e4 * 4];
    }
    __syncthreads();   // B0: flags + g1s visible

    const int f12 = sflag[0], f3 = sflag[1];
    const int nel = count * NNEI;

    // stage sw + raw mask via cp.async (group 2) — overlaps qw projection
    {
        const float* swsrc = sw + (size_t)locbase * NNEI;
        for (int t2 = tid; t2 < (nel >> 2); t2 += NTHR)
            cp16(ssw8 + t2 * 4, swsrc + t2 * 4);
        if (f12) {
            const char* mb = (const char*)maskRaw + (size_t)locbase * NNEI;
            for (int t2 = tid; t2 < (nel >> 3); t2 += NTHR)
                cp8((char*)mtmp + t2 * 8, mb + t2 * 8);
        } else {
            const char* mb = (const char*)maskRaw + (size_t)locbase * NNEI * 4;
            for (int t2 = tid; t2 < (nel >> 2); t2 += NTHR)
                cp16((char*)mtmp + t2 * 16, mb + t2 * 16);
        }
        asm volatile("cp.async.commit_group;\n" ::: "memory");
    }

    // qw[l][n] = g1[l,:] . Mq[:,n]  (n = tid) — overlaps slab + staging transfers
    {
        float acc[BLOC];
#pragma unroll
        for (int l = 0; l < BLOC; l++) acc[l] = 0.f;
        const float* mq = d_Mq + tid;
#pragma unroll 8
        for (int e = 0; e < NI; e++) {
            float m = mq[e * HC];
#pragma unroll
            for (int l = 0; l < BLOC; l++)
                acc[l] += g1s[l * NI + e] * m;
        }
        __syncthreads();   // B1: g1s reads done (a8t free)
#pragma unroll
        for (int l = 0; l < BLOC; l++) qw[l * HC + tid] = acc[l];
    }

    // drain all prologue groups, convert mask
    asm volatile("cp.async.wait_group 0;\n" ::: "memory");
    __syncthreads();       // B2
    for (int t2 = tid; t2 < nel; t2 += NTHR) {
        int m;
        if (f12)      m = ((const unsigned char*)mtmp)[t2] != 0;
        else if (f3)  m = ((const float*)mtmp)[t2] != 0.f;
        else          m = mtmp[t2] != 0;
        smsk8[t2] = m;
    }
    __syncthreads();       // B3: smsk8 done; spart free

    // thread mappings
    const int wid = tid >> 5, lane = tid & 31;
    const int kq = wid & 3;                    // k-quarter (same across warp -> q broadcast)
    const int jt = ((wid >> 2) << 5) + lane;   // 0..127 (rows; all SMSP residues busy)
    const int cw = tid & 127;                  // wsum column
    const int gw = tid >> 7;                   // wsum row-group (30 rows)
    const int c4 = cw >> 2, co = cw & 3;

    // ---------------- per-location loop ----------------
    for (int il = 0; il < count; il++) {
        // ensure slab il resident (at most 1 newer group pending)
        asm volatile("cp.async.wait_group 1;\n" ::: "memory");
        __syncthreads();   // S1
        float* slab = sm + ((il & 1) ? OFF_SLAB1 : OFF_SLAB0);

        // --- logits: thread (kq, jt<120), single pass over full slab ---
        if (jt < NNEI) {
            const float* gr = slab + jt * NI + kq * 32;
            const int jm = jt & 7;
            const float4* q0 = (const float4*)(qw + il * HC + 0 * NI + kq * 32);
            const float4* q1 = (const float4*)(qw + il * HC + 1 * NI + kq * 32);
            const float4* q2 = (const float4*)(qw + il * HC + 2 * NI + kq * 32);
            const float4* q3 = (const float4*)(qw + il * HC + 3 * NI + kq * 32);
            float p0 = 0.f, p1 = 0.f, p2 = 0.f, p3 = 0.f;
#pragma unroll
            for (int i = 0; i < 8; i++) {
                float4 g = *(const float4*)(gr + ((i ^ jm) << 2));
                float4 a = q0[i]; p0 += g.x*a.x + g.y*a.y + g.z*a.z + g.w*a.w;
                float4 b = q1[i]; p1 += g.x*b.x + g.y*b.y + g.z*b.z + g.w*b.w;
                float4 c = q2[i]; p2 += g.x*c.x + g.y*c.y + g.z*c.z + g.w*c.w;
                float4 d = q3[i]; p3 += g.x*d.x + g.y*d.y + g.z*d.z + g.w*d.w;
            }
            spart[kq * HC + 0 * NI + jt] = p0;
            spart[kq * HC + 1 * NI + jt] = p1;
            spart[kq * HC + 2 * NI + jt] = p2;
            spart[kq * HC + 3 * NI + jt] = p3;
        }
        __syncthreads();   // S2

        // --- masked softmax * sw (one warp per head) ---
        if (tid < 128) {
            int h = tid >> 5, ln = tid & 31;
            float lv[4]; int mk[4];
            float mx = -INFINITY;
#pragma unroll
            for (int q = 0; q < 4; q++) {
                int j = ln + q * 32;
                int in = (j < NNEI) ? smsk8[il * NNEI + j] : 0;
                float L = -INFINITY;
                if (in) L = spart[h * NI + j] + spart[HC + h * NI + j]
                          + spart[2 * HC + h * NI + j] + spart[3 * HC + h * NI + j];
                lv[q] = L; mk[q] = in;
                mx = fmaxf(mx, L);
            }
#pragma unroll
            for (int off = 16; off > 0; off >>= 1)
                mx = fmaxf(mx, __shfl_xor_sync(0xFFFFFFFFu, mx, off));
            float ev[4];
            float sum = 0.f;
#pragma unroll
            for (int q = 0; q < 4; q++) {
                ev[q] = mk[q] ? __expf(lv[q] - mx) : 0.f;
                sum += ev[q];
            }
#pragma unroll
            for (int off = 16; off > 0; off >>= 1)
                sum += __shfl_xor_sync(0xFFFFFFFFu, sum, off);
            float inv = (sum > 0.f) ? (1.f / sum) : 0.f;
#pragma unroll
            for (int q = 0; q < 4; q++) {
                int j = ln + q * 32;
                if (j < NNEI)
                    swt4[j * 4 + h] = mk[q] ? ev[q] * inv * ssw8[il * NNEI + j] : 0.f;
            }
        }
        __syncthreads();   // S3

        // --- weighted sum: group gw owns rows [30*gw, 30*gw+30) ---
        {
            float s0 = 0.f, s1 = 0.f, s2 = 0.f, s3 = 0.f;
            int j0 = gw * 30;
#pragma unroll
            for (int t = 0; t < 30; t++) {
                int j = j0 + t;
                float g = slab[j * NI + (((c4 ^ (j & 7)) << 2) | co)];
                float4 w = *(const float4*)&swt4[j * 4];
                s0 += w.x * g; s1 += w.y * g; s2 += w.z * g; s3 += w.w * g;
            }
            spart[gw * HC + 0 * NI + cw] = s0;
            spart[gw * HC + 1 * NI + cw] = s1;
            spart[gw * HC + 2 * NI + cw] = s2;
            spart[gw * HC + 3 * NI + cw] = s3;
        }
        __syncthreads();   // S4: slab free + partials visible

        // prefetch slab il+2 into the buffer just freed (stays in flight across loc il+1)
        if (il + 2 < count)
            issue_slab(sm + ((il & 1) ? OFF_SLAB1 : OFF_SLAB0),
                       gg1 + (size_t)(locbase + il + 2) * SLABF, tid);

        a8t[(tid << 4) + il] = spart[tid] + spart[HC + tid]
                             + spart[2 * HC + tid] + spart[3 * HC + tid];
    }
    __syncthreads();

    // ---------------- fused output GEMM: out[l][128] = a[l][512] @ W2 + bh ----------------
    {
        int i = tid & 127, h2 = tid >> 7;
        float acc[BLOC];
#pragma unroll
        for (int l = 0; l < BLOC; l++) acc[l] = 0.f;
        const float* w2p = d_W2 + (size_t)(h2 * NI) * NI + i;
#pragma unroll 4
        for (int k = 0; k < 128; k++) {
            float w2 = w2p[k * NI];
            const float* ap = a8t + ((h2 * 128 + k) << 4);
            float4 v0 = *(const float4*)ap;
            float4 v1 = *(const float4*)(ap + 4);
            float4 v2 = *(const float4*)(ap + 8);
            float2 v3 = *(const float2*)(ap + 12);
            acc[0]  += v0.x * w2; acc[1]  += v0.y * w2;
            acc[2]  += v0.z * w2; acc[3]  += v0.w * w2;
            acc[4]  += v1.x * w2; acc[5]  += v1.y * w2;
            acc[6]  += v1.z * w2; acc[7]  += v1.w * w2;
            acc[8]  += v2.x * w2; acc[9]  += v2.y * w2;
            acc[10] += v2.z * w2; acc[11] += v2.w * w2;
            acc[12] += v3.x * w2; acc[13] += v3.y * w2;
        }
        __syncthreads();
#pragma unroll
        for (int l = 0; l < BLOC; l++)
            qw[h2 * (BLOC * NI) + l * NI + i] = acc[l];   // reuse qw as partials
    }
    __syncthreads();
    for (int o = tid; o < BLOC * NI; o += NTHR) {
        int l = o >> 7, ii = o & 127;
        if (l < count) {
            float v = qw[o] + qw[BLOC * NI + o]
                    + qw[2 * BLOC * NI + o] + qw[3 * BLOC * NI + o] + bh[ii];
            out[(size_t)(locbase + l) * NI + ii] = v;
        }
    }
}

// ---------------- launch ----------------
extern "C" void kernel_launch(void* const* d_in, const int* in_sizes, int n_in,
                              void* d_out, int out_size)
{
    const float* g1   = (const float*)d_in[0];
    const float* gg1  = (const float*)d_in[1];
    const void*  mask = d_in[2];
    const float* sw   = (const float*)d_in[3];
    const float* Wq   = (const float*)d_in[4];
    const float* Wkv  = (const float*)d_in[5];
    const float* Wh   = (const float*)d_in[6];
    const float* bh   = (const float*)d_in[7];
    float* out = (float*)d_out;

    int nloctot = in_sizes[0] / NI;   // 2048

    static int smem_set = 0;
    if (!smem_set) {
        cudaFuncSetAttribute(fused_attn, cudaFuncAttributeMaxDynamicSharedMemorySize, SMEM_BYTES);
        smem_set = 1;
    }

    int grid = (nloctot + BLOC - 1) / BLOC;   // 147

    precompute_kernel<<<512, 256>>>(Wq, Wkv, Wh);
    fused_attn<<<grid, NTHR, SMEM_BYTES>>>(g1, gg1, mask, sw, bh, out, nloctot);
}

// round 10
// speedup vs baseline: 1.5914x; 1.0137x over previous
#include <cuda_runtime.h>
#include <math.h>

#define NI   128
#define ND   32
#define NH   4
#define NNEI 120
#define HC   (NH * NI)   // 512
#define LOCS_PER_CTA 14
#define THREADS 512
#define SLABF (NNEI * NI)   // 15360 floats, XOR-swizzled, stride 128

typedef unsigned long long u64t;

// ---------------- scratch (device globals) ----------------
__device__ float g_Mq[NI * HC];       // 128 x 512 : combined q/k projection (incl 1/sqrt(32))
__device__ float g_W2[HC * NI];       // 512 x 128 : combined v-projection @ Wh

// ---------------- K0: precompute Mq and W2 ----------------
__global__ void weights_prep_kernel(const float* __restrict__ Wq,
                                    const float* __restrict__ Wkv,
                                    const float* __restrict__ Wh)
{
    const int gid = blockIdx.x * blockDim.x + threadIdx.x;
    if (gid < NI * HC) {
        const int e = gid >> 9;
        const int hc = gid & 511;
        const int h = hc >> 7;
        const int c = hc & 127;
        float s = 0.f;
#pragma unroll
        for (int d = 0; d < ND; d++)
            s += Wq[e * 128 + d * 4 + h] * Wkv[c * 640 + d * 4 + h];
        g_Mq[gid] = s * 0.17677669529663687f;   // 1/sqrt(32)
    } else {
        const int g = gid - NI * HC;
        const int r = g >> 7;          // h*128 + c
        const int i = g & 127;
        const int h = r >> 7;
        const int c = r & 127;
        float s = 0.f;
#pragma unroll 8
        for (int ip = 0; ip < 128; ip++)
            s += Wkv[c * 640 + (32 + ip) * 4 + h] * Wh[(h * 128 + ip) * 128 + i];
        g_W2[g] = s;
    }
}

// ---------------- f32x2 packed helpers ----------------
__device__ __forceinline__ u64t pk2(float x, float y)
{
    u64t r;
    asm("mov.b64 %0, {%1, %2};" : "=l"(r) : "f"(x), "f"(y));
    return r;
}
__device__ __forceinline__ void ffma2(u64t& d, u64t a, u64t b)
{
    asm("fma.rn.f32x2 %0, %1, %2, %0;" : "+l"(d) : "l"(a), "l"(b));
}
__device__ __forceinline__ void unpk2(u64t v, float& x, float& y)
{
    asm("mov.b64 {%0, %1}, %2;" : "=f"(x), "=f"(y) : "l"(v));
}

// ---------------- smem float layout (all 16B-aligned) ----------------
#define SO_SLAB0 0                         // 15360
#define SO_SLAB1 15360                     // 15360
#define SO_QW    30720                     // 7168 = 14*512  qwT[il][c*4+h] (reused as epi partials)
#define SO_ACC   37888                     // 8192 = 512*16  accT[hc][l] stride 16 (g1p overlaid)
#define SO_PART  46080                     // 2048  (mask staging overlaid in prologue)
#define SO_WT    48128                     // 512   wt[j*4 + h]
#define SO_SW    48640                     // 1696
#define SO_MSK   50336                     // 1696 ints
#define SO_FLAG  52032                     // flags
#define SMEM_FLOATS (SO_FLAG + 8)
#define SMEM_BYTES  (SMEM_FLOATS * 4)      // ~208 KB -> 1 CTA/SM

__device__ __forceinline__ void cpa16(void* dst, const void* src)
{
    unsigned s = (unsigned)__cvta_generic_to_shared(dst);
    asm volatile("cp.async.cg.shared.global [%0], [%1], 16;\n" :: "r"(s), "l"(src));
}
__device__ __forceinline__ void cpa8(void* dst, const void* src)
{
    unsigned s = (unsigned)__cvta_generic_to_shared(dst);
    asm volatile("cp.async.ca.shared.global [%0], [%1], 8;\n" :: "r"(s), "l"(src));
}
__device__ __forceinline__ void cpa_commit()
{
    asm volatile("cp.async.commit_group;\n" ::: "memory");
}

__device__ __forceinline__ void stage_slab(float* dst, const float* gsrc, int tid)
{
#pragma unroll
    for (int w = 0; w < 8; w++) {
        const int idx = tid + w * THREADS;
        if (idx < SLABF / 4) {
            const int j = idx >> 5, q = idx & 31;
            cpa16(dst + j * NI + ((q ^ (j & 7)) << 2), gsrc + idx * 4);
        }
    }
    cpa_commit();
}

__global__ __launch_bounds__(THREADS, 1) void attn_main(
    const float* __restrict__ g1,
    const float* __restrict__ gg1,
    const void*  __restrict__ maskRaw,
    const float* __restrict__ sw,
    const float* __restrict__ bh,
    float* __restrict__ out,
    int nloctot)
{
    extern __shared__ float sm[];
    float* qw     = sm + SO_QW;             // qwT per loc: [c*4 + h]
    float* accT   = sm + SO_ACC;
    float* g1p    = accT;                   // prologue overlay: g1p[e*16 + l]
    float* part   = sm + SO_PART;
    int*   mstage = (int*)part;             // prologue overlay
    float* wt     = sm + SO_WT;
    float* sws    = sm + SO_SW;
    int*   msks   = (int*)(sm + SO_MSK);
    int*   flags  = (int*)(sm + SO_FLAG);

    const int tid = threadIdx.x;
    const int locbase = blockIdx.x * LOCS_PER_CTA;
    const int count = min(LOCS_PER_CTA, nloctot - locbase);
    if (count <= 0) return;

    if (tid == 0) { flags[0] = 0; flags[1] = 0; }

    // prefetch slabs for loc0 and loc1
    stage_slab(sm + SO_SLAB0, gg1 + (size_t)locbase * SLABF, tid);
    stage_slab(sm + SO_SLAB1,
               gg1 + (size_t)(locbase + (count > 1 ? 1 : 0)) * SLABF, tid);

    // mask dtype detection from first 1KB (deterministic)
    if (tid < 64) {
        const uint4 v = ((const uint4*)maskRaw)[tid];
        const unsigned orw = v.x | v.y | v.z | v.w;
        if (orw & 0x00FFFF00u) atomicOr(&flags[0], 1);
        if (orw & 0xFF000000u) atomicOr(&flags[1], 1);
    }
    // g1 rows staged TRANSPOSED: g1p[e*16 + l]
    for (int idx = tid; idx < count * NI; idx += THREADS) {
        const int l = idx >> 7, e = idx & 127;
        g1p[e * 16 + l] = g1[(size_t)(locbase + l) * NI + e];
    }
    __syncthreads();   // B0

    const int f12 = flags[0], f3 = flags[1];
    const int nel = count * NNEI;

    // stage sw + raw mask via cp.async — overlaps qw projection
    {
        const float* swsrc = sw + (size_t)locbase * NNEI;
        for (int t2 = tid; t2 < (nel >> 2); t2 += THREADS)
            cpa16(sws + t2 * 4, swsrc + t2 * 4);
        if (f12) {
            const char* mb = (const char*)maskRaw + (size_t)locbase * NNEI;
            for (int t2 = tid; t2 < (nel >> 3); t2 += THREADS)
                cpa8((char*)mstage + t2 * 8, mb + t2 * 8);
        } else {
            const char* mb = (const char*)maskRaw + (size_t)locbase * NNEI * 4;
            for (int t2 = tid; t2 < (nel >> 2); t2 += THREADS)
                cpa16((char*)mstage + t2 * 16, mb + t2 * 16);
        }
        cpa_commit();
    }

    // qw projection (packed): acc pair (l,l+1) += (g1p[e][l],g1p[e][l+1]) * (m,m)
    {
        u64t acc[7];
#pragma unroll
        for (int t = 0; t < 7; t++) acc[t] = 0ull;
        const float* mq = g_Mq + tid;
#pragma unroll 4
        for (int e = 0; e < NI; e++) {
            const float m = mq[e * HC];
            const u64t mm = pk2(m, m);
            const ulonglong2* gp = (const ulonglong2*)(g1p + e * 16);
            const ulonglong2 ga = gp[0];
            const ulonglong2 gb = gp[1];
            const ulonglong2 gc = gp[2];
            const u64t gd = *(const u64t*)(g1p + e * 16 + 12);
            ffma2(acc[0], ga.x, mm); ffma2(acc[1], ga.y, mm);
            ffma2(acc[2], gb.x, mm); ffma2(acc[3], gb.y, mm);
            ffma2(acc[4], gc.x, mm); ffma2(acc[5], gc.y, mm);
            ffma2(acc[6], gd,   mm);
        }
        __syncthreads();   // B1: g1p reads done (accT free)
        // store head-interleaved: qwT[il][c*4 + h], n = tid = h*128+c
        const int c = tid & 127, h = tid >> 7;
#pragma unroll
        for (int t = 0; t < 7; t++) {
            float x, y;
            unpk2(acc[t], x, y);
            qw[(2 * t + 0) * HC + c * 4 + h] = x;
            qw[(2 * t + 1) * HC + c * 4 + h] = y;
        }
    }

    // drain prologue staging, convert mask (2 fixed strided iters: nel <= 1680)
    asm volatile("cp.async.wait_group 0;\n" ::: "memory");
    __syncthreads();       // B2
    {
#pragma unroll
        for (int w = 0; w < 4; w++) {
            const int t2 = tid + w * THREADS;
            if (t2 < nel) {
                int m;
                if (f12)      m = ((const unsigned char*)mstage)[t2] != 0;
                else if (f3)  m = ((const float*)mstage)[t2] != 0.f;
                else          m = mstage[t2] != 0;
                msks[t2] = m;
            }
        }
    }
    __syncthreads();       // B3

    // thread mappings
    const int wid = tid >> 5, lane = tid & 31;
    const int kq = wid & 3;
    const int jt = ((wid >> 2) << 5) + lane;
    const int cw = tid & 127;
    const int gw = tid >> 7;
    const int c4 = cw >> 2, co = cw & 3;

    // ---------------- per-location loop ----------------
    for (int il = 0; il < count; il++) {
        asm volatile("cp.async.wait_group 1;\n" ::: "memory");
        __syncthreads();   // S1
        float* slab = sm + ((il & 1) ? SO_SLAB1 : SO_SLAB0);

        // --- logits (packed pairs over heads) ---
        if (jt < NNEI) {
            const float* gr = slab + jt * NI + kq * 32;
            const int jm = jt & 7;
            const float* qT = qw + il * HC + kq * 128;   // qwT: [c*4+h], c base = kq*32
            u64t P01 = 0ull, P23 = 0ull;
#pragma unroll
            for (int i = 0; i < 8; i++) {
                const float4 g = *(const float4*)(gr + ((i ^ jm) << 2));
                const ulonglong2* qq = (const ulonglong2*)(qT + i * 16);
                const ulonglong2 q0 = qq[0], q1 = qq[1], q2 = qq[2], q3 = qq[3];
                const u64t gx = pk2(g.x, g.x), gy = pk2(g.y, g.y);
                const u64t gz = pk2(g.z, g.z), gv = pk2(g.w, g.w);
                ffma2(P01, gx, q0.x); ffma2(P23, gx, q0.y);
                ffma2(P01, gy, q1.x); ffma2(P23, gy, q1.y);
                ffma2(P01, gz, q2.x); ffma2(P23, gz, q2.y);
                ffma2(P01, gv, q3.x); ffma2(P23, gv, q3.y);
            }
            float p0, p1, p2, p3;
            unpk2(P01, p0, p1);
            unpk2(P23, p2, p3);
            part[kq * HC + 0 * NI + jt] = p0;
            part[kq * HC + 1 * NI + jt] = p1;
            part[kq * HC + 2 * NI + jt] = p2;
            part[kq * HC + 3 * NI + jt] = p3;
        }
        __syncthreads();   // S2

        // --- masked softmax * sw (one warp per head) ---
        if (tid < 128) {
            const int h = tid >> 5, ln = tid & 31;
            float lv[4]; int mk[4];
            float mx = -INFINITY;
#pragma unroll
            for (int q = 0; q < 4; q++) {
                const int j = ln + q * 32;
                const int in = (j < NNEI) ? msks[il * NNEI + j] : 0;
                float L = -INFINITY;
                if (in) L = part[h * NI + j] + part[HC + h * NI + j]
                          + part[2 * HC + h * NI + j] + part[3 * HC + h * NI + j];
                lv[q] = L; mk[q] = in;
                mx = fmaxf(mx, L);
            }
#pragma unroll
            for (int off = 16; off > 0; off >>= 1)
                mx = fmaxf(mx, __shfl_xor_sync(0xFFFFFFFFu, mx, off));
            float ev[4];
            float sum = 0.f;
#pragma unroll
            for (int q = 0; q < 4; q++) {
                ev[q] = mk[q] ? __expf(lv[q] - mx) : 0.f;
                sum += ev[q];
            }
#pragma unroll
            for (int off = 16; off > 0; off >>= 1)
                sum += __shfl_xor_sync(0xFFFFFFFFu, sum, off);
            const float inv = (sum > 0.f) ? (1.f / sum) : 0.f;
#pragma unroll
            for (int q = 0; q < 4; q++) {
                const int j = ln + q * 32;
                if (j < NNEI)
                    wt[j * 4 + h] = mk[q] ? ev[q] * inv * sws[il * NNEI + j] : 0.f;
            }
        }
        __syncthreads();   // S3

        // --- weighted sum (packed pairs over heads) ---
        {
            u64t S01 = 0ull, S23 = 0ull;
            const int j0 = gw * 30;
#pragma unroll
            for (int t = 0; t < 30; t++) {
                const int j = j0 + t;
                const float g = slab[j * NI + (((c4 ^ (j & 7)) << 2) | co)];
                const ulonglong2 wv = *(const ulonglong2*)(wt + j * 4);
                const u64t gg = pk2(g, g);
                ffma2(S01, gg, wv.x);
                ffma2(S23, gg, wv.y);
            }
            float s0, s1, s2, s3;
            unpk2(S01, s0, s1);
            unpk2(S23, s2, s3);
            part[gw * HC + 0 * NI + cw] = s0;
            part[gw * HC + 1 * NI + cw] = s1;
            part[gw * HC + 2 * NI + cw] = s2;
            part[gw * HC + 3 * NI + cw] = s3;
        }
        __syncthreads();   // S4: slab free + partials visible

        if (il + 2 < count)
            stage_slab(sm + ((il & 1) ? SO_SLAB1 : SO_SLAB0),
                       gg1 + (size_t)(locbase + il + 2) * SLABF, tid);

        accT[(tid << 4) + il] = part[tid] + part[HC + tid]
                              + part[2 * HC + tid] + part[3 * HC + tid];
    }
    __syncthreads();

    // ---------------- fused output GEMM (packed): out[l][128] = a[l][512] @ W2 + bh ----------------
    {
        const int i = tid & 127, h2 = tid >> 7;
        u64t acc[7];
#pragma unroll
        for (int t = 0; t < 7; t++) acc[t] = 0ull;
        const float* w2p = g_W2 + (size_t)(h2 * NI) * NI + i;
#pragma unroll 4
        for (int k = 0; k < 128; k++) {
            const float w2 = w2p[k * NI];
            const u64t ww = pk2(w2, w2);
            const float* ap = accT + ((h2 * 128 + k) << 4);
            const ulonglong2* app = (const ulonglong2*)ap;
            const ulonglong2 v0 = app[0];
            const ulonglong2 v1 = app[1];
            const ulonglong2 v2 = app[2];
            const u64t v3 = *(const u64t*)(ap + 12);
            ffma2(acc[0], v0.x, ww); ffma2(acc[1], v0.y, ww);
            ffma2(acc[2], v1.x, ww); ffma2(acc[3], v1.y, ww);
            ffma2(acc[4], v2.x, ww); ffma2(acc[5], v2.y, ww);
            ffma2(acc[6], v3,   ww);
        }
        __syncthreads();
#pragma unroll
        for (int t = 0; t < 7; t++) {
            float x, y;
            unpk2(acc[t], x, y);
            qw[h2 * (LOCS_PER_CTA * NI) + (2 * t + 0) * NI + i] = x;
            qw[h2 * (LOCS_PER_CTA * NI) + (2 * t + 1) * NI + i] = y;
        }
    }
    __syncthreads();
    for (int o = tid; o < LOCS_PER_CTA * NI; o += THREADS) {
        const int l = o >> 7, ii = o & 127;
        if (l < count) {
            const float v = qw[o] + qw[LOCS_PER_CTA * NI + o]
                          + qw[2 * LOCS_PER_CTA * NI + o]
                          + qw[3 * LOCS_PER_CTA * NI + o] + bh[ii];
            out[(size_t)(locbase + l) * NI + ii] = v;
        }
    }
}

// ---------------- launch ----------------
extern "C" void kernel_launch(void* const* d_in, const int* in_sizes, int n_in,
                              void* d_out, int out_size)
{
    const float* g1   = (const float*)d_in[0];
    const float* gg1  = (const float*)d_in[1];
    const void*  mask = d_in[2];
    const float* sw   = (const float*)d_in[3];
    const float* Wq   = (const float*)d_in[4];
    const float* Wkv  = (const float*)d_in[5];
    const float* Wh   = (const float*)d_in[6];
    const float* bh   = (const float*)d_in[7];
    float* out = (float*)d_out;

    const int nloctot = in_sizes[0] / NI;   // 2048

    static int smem_cfg = 0;
    if (!smem_cfg) {
        cudaFuncSetAttribute(attn_main, cudaFuncAttributeMaxDynamicSharedMemorySize, SMEM_BYTES);
        smem_cfg = 1;
    }

    const int grid = (nloctot + LOCS_PER_CTA - 1) / LOCS_PER_CTA;   // 147

    weights_prep_kernel<<<512, 256>>>(Wq, Wkv, Wh);
    attn_main<<<grid, THREADS, SMEM_BYTES>>>(g1, gg1, mask, sw, bh, out, nloctot);
}